// round 14
// baseline (speedup 1.0000x reference)
#include <cuda_runtime.h>
#include <cuda_bf16.h>
#include <cstdint>

// ---------------------------------------------------------------------------
//   mega(1): c2half+cb norms | cvt planes | conv1 | zero gmax/fn2
//   conv2 (WIDE)  -> g_f2i {hi,lo} u32                       [875us]
//   conv3 (WIDE)  -> f3 planes + per-token norm2 atomics     [~780us]
//   dist_pass1 (32x64 warps, CTA 64x256, launch#4 profiled): 1-term GEMM
//   dist_refine: bound-based candidate rescore in fp32 -> g_final
//   R14: pass1 warp tile 64x32 -> 32x64: 96 B LDS/MMA (was 192) at SAME
//        16 warps/SM. LDS:tensor goes 1:1 -> 1:2 => tensor-bound.
// ---------------------------------------------------------------------------

__device__ uint32_t g_f1i[16u * 192u * 128u * 128u];
__device__ uint32_t g_f2i[16u * 384u * 64u * 64u];
__device__ __nv_bfloat16 g_f3h[16384u * 768u];
__device__ __nv_bfloat16 g_f3l[16384u * 768u];
__device__ __nv_bfloat16 g_w2h[384u * 1728u];
__device__ __nv_bfloat16 g_w2l[384u * 1728u];
__device__ __nv_bfloat16 g_w3h[768u * 3456u];
__device__ __nv_bfloat16 g_w3l[768u * 3456u];
__device__ __nv_bfloat16 g_cbh[8192u * 768u];
__device__ __nv_bfloat16 g_cbl[8192u * 768u];
__device__ float g_c2h[8192];
__device__ float g_fn2[2 * 16384];           // per-token sum fh^2, fl^2
__device__ uint32_t g_clmax2, g_ctmax2;      // max over codes: sum cl^2, sum (ch+cl)^2
__device__ uint32_t g_gmax[16384u * 1024u];  // per (token, 8-code group) packed max
__device__ uint32_t g_final[16384];          // winning code per token

// ------------------------------ helpers -----------------------------------
__device__ __forceinline__ uint32_t smem_u32(const void* p) {
    uint32_t a;
    asm("{ .reg .u64 t; cvta.to.shared.u64 t, %1; cvt.u32.u64 %0, t; }"
        : "=r"(a) : "l"(p));
    return a;
}
__device__ __forceinline__ void ldsm4(uint32_t* r, uint32_t addr) {
    asm volatile("ldmatrix.sync.aligned.m8n8.x4.shared.b16 {%0,%1,%2,%3}, [%4];"
        : "=r"(r[0]), "=r"(r[1]), "=r"(r[2]), "=r"(r[3]) : "r"(addr));
}
__device__ __forceinline__ void mma_bf16(float* c, const uint32_t* a, const uint32_t* b) {
    asm volatile("mma.sync.aligned.m16n8k16.row.col.f32.bf16.bf16.f32 "
        "{%0,%1,%2,%3}, {%4,%5,%6,%7}, {%8,%9}, {%0,%1,%2,%3};"
        : "+f"(c[0]), "+f"(c[1]), "+f"(c[2]), "+f"(c[3])
        : "r"(a[0]), "r"(a[1]), "r"(a[2]), "r"(a[3]), "r"(b[0]), "r"(b[1]));
}
__device__ __forceinline__ uint32_t prmt(uint32_t a, uint32_t b, uint32_t c) {
    uint32_t d;
    asm("prmt.b32 %0, %1, %2, %3;" : "=r"(d) : "r"(a), "r"(b), "r"(c));
    return d;
}
__device__ __forceinline__ void cp16(uint32_t dst, const void* src) {
    asm volatile("cp.async.cg.shared.global [%0], [%1], 16;"
                 :: "r"(dst), "l"(src) : "memory");
}
__device__ __forceinline__ void sts128(uint32_t addr, uint32_t a, uint32_t b,
                                       uint32_t c, uint32_t d) {
    asm volatile("st.shared.v4.b32 [%0], {%1,%2,%3,%4};"
                 :: "r"(addr), "r"(a), "r"(b), "r"(c), "r"(d) : "memory");
}
__device__ __forceinline__ unsigned long long pack_key(float s, int v) {
    unsigned u = __float_as_uint(s);
    u = (u & 0x80000000u) ? ~u : (u | 0x80000000u);
    return ((unsigned long long)u << 32) | (unsigned)(0xFFFFFFFFu - (unsigned)v);
}
__device__ __forceinline__ uint32_t pkf(float s) {      // monotonic float->u32
    uint32_t u = __float_as_uint(s);
    return (u & 0x80000000u) ? ~u : (u | 0x80000000u);
}
__device__ __forceinline__ float upkf(uint32_t u) {
    u = (u & 0x80000000u) ? (u & 0x7FFFFFFFu) : ~u;
    return __uint_as_float(u);
}
__device__ __forceinline__ uint32_t pack_hl(float v) {
    __nv_bfloat16 h = __float2bfloat16(v);
    float hf = __bfloat162float(h);
    __nv_bfloat16 l = __float2bfloat16(v - hf);
    return ((uint32_t)__bfloat16_as_ushort(l) << 16) | __bfloat16_as_ushort(h);
}

static constexpr int TILE = 128 * 48;      // 6144 B (one plane, 128 rows, K16)
static constexpr int STAGE = 4 * TILE;     // Ah,Al,Bh,Bl = 24576 B
static constexpr int NSTAGE = 4;
static constexpr int GEMM_SMEM = NSTAGE * STAGE + 512;

// pass1: A tile 64 rows (tokens), B tile 256 rows (codes), K-chunk 16
static constexpr int TILE_A1 = 64 * 48;    // 3072 B
static constexpr int TILE_B1 = 256 * 48;   // 12288 B
static constexpr int STAGE1 = TILE_A1 + TILE_B1;   // 15360 B
static constexpr int NST1 = 4;
static constexpr int P1_SMEM = NST1 * STAGE1 + 1024;   // 62464 B

#define WAITG(n) asm volatile("cp.async.wait_group %0;" :: "n"(n) : "memory")

// ===========================================================================
// WIDE conv2 kernel (measured 875us): 128 threads, 4 warps of 64x64, 2 CTA/SM
// ===========================================================================
__global__ __launch_bounds__(128, 2) void mma_wide_c2(
    const void* __restrict__ pa0, const void* __restrict__ pa1,
    const void* __restrict__ pb0,
    const float* __restrict__ vec, void* __restrict__ o0, int K)
{
    extern __shared__ char sm[];
    const uint32_t sb = smem_u32(sm);
    const int tid = threadIdx.x, wid = tid >> 5, lane = tid & 31;
    const int m0 = blockIdx.x * 128, n0 = blockIdx.y * 128;
    const int NT = K >> 4;

    float* vecs = (float*)(sm + NSTAGE * STAGE);
    vecs[tid] = vec[m0 + tid];

    const char* dirA_h = (const char*)pa0 + (size_t)(m0 + tid) * 1728 * 2;
    const char* dirA_l = (const char*)pa1 + (size_t)(m0 + tid) * 1728 * 2;
    int n = n0 + tid;
    int bb = n >> 12, rem = n & 4095;
    int oy = rem >> 6, ox = rem & 63;
    const uint32_t* gsrc = (const uint32_t*)pb0 + (size_t)bb * (192u * 128u * 128u);
    int giy0 = 2 * oy - 1, gix0 = 2 * ox - 1;

    const uint32_t loff = (uint32_t)tid * 48;
    uint32_t gregs[16];
    uint32_t gst_hi = 0, gst_lo = 0;

    auto issue = [&](int kt, int s) {
        const uint32_t st = sb + (uint32_t)s * STAGE + loff;
        cp16(st,             dirA_h + kt * 32);
        cp16(st + 16,        dirA_h + kt * 32 + 16);
        cp16(st + TILE,      dirA_l + kt * 32);
        cp16(st + TILE + 16, dirA_l + kt * 32 + 16);
        asm volatile("cp.async.commit_group;" ::: "memory");
        const int k0 = kt * 16;
#pragma unroll
        for (int j = 0; j < 16; j++) {
            int k = k0 + j;
            int ci = (k * 7282) >> 16;
            int r = k - ci * 9;
            int ky = (r * 11) >> 5;
            int kx = r - ky * 3;
            int iy = giy0 + ky, ix = gix0 + kx;
            bool ok = (iy >= 0) && (iy < 128) && (ix >= 0) && (ix < 128);
            gregs[j] = ok ? gsrc[(size_t)((ci * 128 + iy) * 128 + ix)] : 0u;
        }
        gst_hi = st + 2 * TILE;
        gst_lo = gst_hi + TILE;
    };
    auto finish = [&]() {
        sts128(gst_hi,      prmt(gregs[0],  gregs[1],  0x5410), prmt(gregs[2],  gregs[3],  0x5410),
                            prmt(gregs[4],  gregs[5],  0x5410), prmt(gregs[6],  gregs[7],  0x5410));
        sts128(gst_hi + 16, prmt(gregs[8],  gregs[9],  0x5410), prmt(gregs[10], gregs[11], 0x5410),
                            prmt(gregs[12], gregs[13], 0x5410), prmt(gregs[14], gregs[15], 0x5410));
        sts128(gst_lo,      prmt(gregs[0],  gregs[1],  0x7632), prmt(gregs[2],  gregs[3],  0x7632),
                            prmt(gregs[4],  gregs[5],  0x7632), prmt(gregs[6],  gregs[7],  0x7632));
        sts128(gst_lo + 16, prmt(gregs[8],  gregs[9],  0x7632), prmt(gregs[10], gregs[11], 0x7632),
                            prmt(gregs[12], gregs[13], 0x7632), prmt(gregs[14], gregs[15], 0x7632));
    };

    const int wm = wid & 1, wn = wid >> 1;
    const int q = lane >> 3, rr = lane & 7;
    const uint32_t a_off = (uint32_t)((wm * 64 + (q & 1) * 8 + rr) * 48 + (q >> 1) * 16);
    const uint32_t b_off = (uint32_t)(((q >> 1) * 8 + rr) * 48 + (q & 1) * 16)
                         + (uint32_t)(wn * 64) * 48;

    float acc[4][8][4];
#pragma unroll
    for (int i = 0; i < 4; i++)
#pragma unroll
        for (int j = 0; j < 8; j++)
#pragma unroll
            for (int e = 0; e < 4; e++) acc[i][j][e] = 0.f;

    issue(0, 0); finish();
    issue(1, 1); finish();
    issue(2, 2); finish();

#pragma unroll 1
    for (int kt = 0; kt < NT; kt++) {
        if (kt + 2 < NT)      WAITG(2);
        else if (kt + 1 < NT) WAITG(1);
        else                  WAITG(0);
        __syncthreads();

        const int s = kt & 3;
        const uint32_t Ah_b = sb + s * STAGE;
        const uint32_t Al_b = Ah_b + TILE;
        const uint32_t Bh_b = Ah_b + 2 * TILE;
        const uint32_t Bl_b = Ah_b + 3 * TILE;

        uint32_t Bh[4][4], Bl[4][4];
#pragma unroll
        for (int ni = 0; ni < 4; ni++) {
            ldsm4(Bh[ni], Bh_b + b_off + ni * 16 * 48);
            ldsm4(Bl[ni], Bl_b + b_off + ni * 16 * 48);
        }
        const bool doNext = (kt + 3 < NT);
        if (doNext) issue(kt + 3, (kt + 3) & 3);

#pragma unroll
        for (int mi = 0; mi < 4; mi++) {
            uint32_t Ah[4], Al[4];
            ldsm4(Ah, Ah_b + a_off + mi * 768);
            ldsm4(Al, Al_b + a_off + mi * 768);
#pragma unroll
            for (int nj = 0; nj < 8; nj++)
                mma_bf16(acc[mi][nj], Ah, &Bh[nj >> 1][(nj & 1) * 2]);
#pragma unroll
            for (int nj = 0; nj < 8; nj++)
                mma_bf16(acc[mi][nj], Ah, &Bl[nj >> 1][(nj & 1) * 2]);
#pragma unroll
            for (int nj = 0; nj < 8; nj++)
                mma_bf16(acc[mi][nj], Al, &Bh[nj >> 1][(nj & 1) * 2]);
        }
        if (doNext) finish();
    }

    const int tg = lane >> 2, tp = lane & 3;
    uint32_t* Ci = (uint32_t*)o0;
    const int obb = n0 >> 12;
    const int sp0 = (n0 & 4095) + wn * 64;
#pragma unroll
    for (int mi = 0; mi < 4; mi++)
#pragma unroll
        for (int h = 0; h < 2; h++) {
            int ml = wm * 64 + mi * 16 + tg + h * 8;
            int m = m0 + ml;
            float bv = vecs[ml];
            uint32_t* rowp = Ci + ((size_t)obb * 384 + m) * 4096;
#pragma unroll
            for (int nj = 0; nj < 8; nj++) {
                float v0 = fmaxf(acc[mi][nj][h * 2 + 0] + bv, 0.f);
                float v1 = fmaxf(acc[mi][nj][h * 2 + 1] + bv, 0.f);
                *(uint2*)(rowp + sp0 + nj * 8 + 2 * tp) =
                    make_uint2(pack_hl(v0), pack_hl(v1));
            }
        }
}

// ===========================================================================
// WIDE conv3 kernel (+ per-token norm2 accumulation in epilogue)
// ===========================================================================
__global__ __launch_bounds__(128, 2) void mma_wide_c3(
    const void* __restrict__ pa0,
    const void* __restrict__ pb0, const void* __restrict__ pb1,
    const float* __restrict__ vec, void* __restrict__ o0,
    void* __restrict__ o1, int K)
{
    extern __shared__ char sm[];
    const uint32_t sb = smem_u32(sm);
    const int tid = threadIdx.x, wid = tid >> 5, lane = tid & 31;
    const int m0 = blockIdx.x * 128, n0 = blockIdx.y * 128;
    const int NT = K >> 4;

    float* vecs = (float*)(sm + NSTAGE * STAGE);
    vecs[tid] = vec[n0 + tid];

    int n = m0 + tid;
    int bb = n >> 10, rem = n & 1023;
    int oy = rem >> 5, ox = rem & 31;
    const uint32_t* gsrc = (const uint32_t*)pa0 + (size_t)bb * (384u * 64u * 64u);
    int giy0 = 2 * oy - 1, gix0 = 2 * ox - 1;
    const char* dirB_h = (const char*)pb0 + (size_t)(n0 + tid) * 3456 * 2;
    const char* dirB_l = (const char*)pb1 + (size_t)(n0 + tid) * 3456 * 2;

    const uint32_t loff = (uint32_t)tid * 48;
    uint32_t gregs[16];
    uint32_t gst_hi = 0, gst_lo = 0;

    auto issue = [&](int kt, int s) {
        const uint32_t st = sb + (uint32_t)s * STAGE + loff;
        cp16(st + 2 * TILE,      dirB_h + kt * 32);
        cp16(st + 2 * TILE + 16, dirB_h + kt * 32 + 16);
        cp16(st + 3 * TILE,      dirB_l + kt * 32);
        cp16(st + 3 * TILE + 16, dirB_l + kt * 32 + 16);
        asm volatile("cp.async.commit_group;" ::: "memory");
        const int k0 = kt * 16;
#pragma unroll
        for (int j = 0; j < 16; j++) {
            int k = k0 + j;
            int ci = (k * 7282) >> 16;
            int r = k - ci * 9;
            int ky = (r * 11) >> 5;
            int kx = r - ky * 3;
            int iy = giy0 + ky, ix = gix0 + kx;
            bool ok = (iy >= 0) && (iy < 64) && (ix >= 0) && (ix < 64);
            gregs[j] = ok ? gsrc[(size_t)((ci * 64 + iy) * 64 + ix)] : 0u;
        }
        gst_hi = st;
        gst_lo = st + TILE;
    };
    auto finish = [&]() {
        sts128(gst_hi,      prmt(gregs[0],  gregs[1],  0x5410), prmt(gregs[2],  gregs[3],  0x5410),
                            prmt(gregs[4],  gregs[5],  0x5410), prmt(gregs[6],  gregs[7],  0x5410));
        sts128(gst_hi + 16, prmt(gregs[8],  gregs[9],  0x5410), prmt(gregs[10], gregs[11], 0x5410),
                            prmt(gregs[12], gregs[13], 0x5410), prmt(gregs[14], gregs[15], 0x5410));
        sts128(gst_lo,      prmt(gregs[0],  gregs[1],  0x7632), prmt(gregs[2],  gregs[3],  0x7632),
                            prmt(gregs[4],  gregs[5],  0x7632), prmt(gregs[6],  gregs[7],  0x7632));
        sts128(gst_lo + 16, prmt(gregs[8],  gregs[9],  0x7632), prmt(gregs[10], gregs[11], 0x7632),
                            prmt(gregs[12], gregs[13], 0x7632), prmt(gregs[14], gregs[15], 0x7632));
    };

    const int wm = wid & 1, wn = wid >> 1;
    const int q = lane >> 3, rr = lane & 7;
    const uint32_t a_off = (uint32_t)((wm * 64 + (q & 1) * 8 + rr) * 48 + (q >> 1) * 16);
    const uint32_t b_off = (uint32_t)(((q >> 1) * 8 + rr) * 48 + (q & 1) * 16)
                         + (uint32_t)(wn * 64) * 48;

    float acc[4][8][4];
#pragma unroll
    for (int i = 0; i < 4; i++)
#pragma unroll
        for (int j = 0; j < 8; j++)
#pragma unroll
            for (int e = 0; e < 4; e++) acc[i][j][e] = 0.f;

    issue(0, 0); finish();
    issue(1, 1); finish();
    issue(2, 2); finish();

#pragma unroll 1
    for (int kt = 0; kt < NT; kt++) {
        if (kt + 2 < NT)      WAITG(2);
        else if (kt + 1 < NT) WAITG(1);
        else                  WAITG(0);
        __syncthreads();

        const int s = kt & 3;
        const uint32_t Ah_b = sb + s * STAGE;
        const uint32_t Al_b = Ah_b + TILE;
        const uint32_t Bh_b = Ah_b + 2 * TILE;
        const uint32_t Bl_b = Ah_b + 3 * TILE;

        uint32_t Bh[4][4], Bl[4][4];
#pragma unroll
        for (int ni = 0; ni < 4; ni++) {
            ldsm4(Bh[ni], Bh_b + b_off + ni * 16 * 48);
            ldsm4(Bl[ni], Bl_b + b_off + ni * 16 * 48);
        }
        const bool doNext = (kt + 3 < NT);
        if (doNext) issue(kt + 3, (kt + 3) & 3);

#pragma unroll
        for (int mi = 0; mi < 4; mi++) {
            uint32_t Ah[4], Al[4];
            ldsm4(Ah, Ah_b + a_off + mi * 768);
            ldsm4(Al, Al_b + a_off + mi * 768);
#pragma unroll
            for (int nj = 0; nj < 8; nj++)
                mma_bf16(acc[mi][nj], Ah, &Bh[nj >> 1][(nj & 1) * 2]);
#pragma unroll
            for (int nj = 0; nj < 8; nj++)
                mma_bf16(acc[mi][nj], Ah, &Bl[nj >> 1][(nj & 1) * 2]);
#pragma unroll
            for (int nj = 0; nj < 8; nj++)
                mma_bf16(acc[mi][nj], Al, &Bh[nj >> 1][(nj & 1) * 2]);
        }
        if (doNext) finish();
    }

    const int tg = lane >> 2, tp = lane & 3;
    __nv_bfloat16* fh = (__nv_bfloat16*)o0;
    __nv_bfloat16* fl = (__nv_bfloat16*)o1;
#pragma unroll
    for (int mi = 0; mi < 4; mi++)
#pragma unroll
        for (int h = 0; h < 2; h++) {
            int m = m0 + wm * 64 + mi * 16 + tg + h * 8;   // token
            __nv_bfloat16* rowh = fh + (size_t)m * 768 + n0;
            __nv_bfloat16* rowl = fl + (size_t)m * 768 + n0;
            float sh2 = 0.f, sl2 = 0.f;
#pragma unroll
            for (int nj = 0; nj < 8; nj++) {
                int nl = wn * 64 + nj * 8 + 2 * tp;
                float v0 = acc[mi][nj][h * 2 + 0] + vecs[nl + 0];
                float v1 = acc[mi][nj][h * 2 + 1] + vecs[nl + 1];
                __nv_bfloat16 h0 = __float2bfloat16(v0);
                __nv_bfloat16 h1 = __float2bfloat16(v1);
                float h0f = __bfloat162float(h0), h1f = __bfloat162float(h1);
                __nv_bfloat16 l0 = __float2bfloat16(v0 - h0f);
                __nv_bfloat16 l1 = __float2bfloat16(v1 - h1f);
                float l0f = __bfloat162float(l0), l1f = __bfloat162float(l1);
                sh2 += h0f * h0f + h1f * h1f;
                sl2 += l0f * l0f + l1f * l1f;
                *(__nv_bfloat162*)(rowh + nl) = __nv_bfloat162(h0, h1);
                *(__nv_bfloat162*)(rowl + nl) = __nv_bfloat162(l0, l1);
            }
            sh2 += __shfl_xor_sync(0xFFFFFFFFu, sh2, 1);
            sh2 += __shfl_xor_sync(0xFFFFFFFFu, sh2, 2);
            sl2 += __shfl_xor_sync(0xFFFFFFFFu, sl2, 1);
            sl2 += __shfl_xor_sync(0xFFFFFFFFu, sl2, 2);
            if (tp == 0) {
                atomicAdd(&g_fn2[2 * m],     sh2);
                atomicAdd(&g_fn2[2 * m + 1], sl2);
            }
        }
}

// ===========================================================================
// dist pass1 (R14): 256 threads, 8 warps of 32x64, CTA tile 64x256, 2 CTA/SM.
// 1-term GEMM fh*ch; 96 B LDS per MMA. Epilogue: per-group atomicMax.
// ===========================================================================
__global__ __launch_bounds__(256, 2) void dist_pass1(
    const void* __restrict__ pa0, const void* __restrict__ pb0,
    const float* __restrict__ vec, int K)
{
    extern __shared__ char sm[];
    const uint32_t sb = smem_u32(sm);
    const int tid = threadIdx.x, wid = tid >> 5, lane = tid & 31;
    const int m0 = blockIdx.x * 64, n0 = blockIdx.y * 256;
    const int NT = K >> 4;

    float* vecs = (float*)(sm + NST1 * STAGE1);
    vecs[tid] = vec[n0 + tid];

    // A loader: threads 0-127, row = tid>>1 (64 rows), half = tid&1
    const int lrow = tid >> 1, lhalf = tid & 1;
    const char* dirA_h = (const char*)pa0 + ((size_t)(m0 + lrow) * 768 + lhalf * 8) * 2;
    const uint32_t a_loff = (uint32_t)(lrow * 48 + lhalf * 16);
    // B loader: all 256 threads, row = tid, 2 x cp16
    const char* dirB_h = (const char*)pb0 + (size_t)(n0 + tid) * 768 * 2;
    const uint32_t b_loff = (uint32_t)(TILE_A1 + tid * 48);

    auto load_chunk = [&](int kt, int s) {
        const uint32_t st = sb + (uint32_t)s * STAGE1;
        if (tid < 128)
            cp16(st + a_loff, dirA_h + kt * 32);
        cp16(st + b_loff,      dirB_h + kt * 32);
        cp16(st + b_loff + 16, dirB_h + kt * 32 + 16);
        asm volatile("cp.async.commit_group;" ::: "memory");
    };

    // warp tiling: 2 (m, 32 rows each) x 4 (n, 64 cols each)
    const int wm = wid & 1, wn = wid >> 1;
    const int q = lane >> 3, rr = lane & 7;
    const uint32_t a_off = (uint32_t)((wm * 32 + (q & 1) * 8 + rr) * 48 + (q >> 1) * 16);
    const uint32_t b_off = (uint32_t)(TILE_A1 + ((q >> 1) * 8 + rr) * 48 + (q & 1) * 16)
                         + (uint32_t)(wn * 64) * 48;

    float acc[2][8][4];
#pragma unroll
    for (int i = 0; i < 2; i++)
#pragma unroll
        for (int j = 0; j < 8; j++)
#pragma unroll
            for (int e = 0; e < 4; e++) acc[i][j][e] = 0.f;

    load_chunk(0, 0);
    load_chunk(1, 1);
    load_chunk(2, 2);

#pragma unroll 1
    for (int kt = 0; kt < NT; kt++) {
        if (kt + 2 < NT)      WAITG(2);
        else if (kt + 1 < NT) WAITG(1);
        else                  WAITG(0);
        __syncthreads();

        const int s = kt & 3;
        const uint32_t st = sb + (uint32_t)s * STAGE1;

        uint32_t Bh[4][4];
#pragma unroll
        for (int ni = 0; ni < 4; ni++)
            ldsm4(Bh[ni], st + b_off + ni * 16 * 48);
        if (kt + 3 < NT) load_chunk(kt + 3, (kt + 3) & 3);

#pragma unroll
        for (int mi = 0; mi < 2; mi++) {
            uint32_t Ah[4];
            ldsm4(Ah, st + a_off + mi * 16 * 48);
#pragma unroll
            for (int nj = 0; nj < 8; nj++)
                mma_bf16(acc[mi][nj], Ah, &Bh[nj >> 1][(nj & 1) * 2]);
        }
    }

    const int tg = lane >> 2, tp = lane & 3;
#pragma unroll
    for (int mi = 0; mi < 2; mi++)
#pragma unroll
        for (int h = 0; h < 2; h++) {
            int t = m0 + wm * 32 + mi * 16 + tg + h * 8;   // token
#pragma unroll
            for (int nj = 0; nj < 8; nj++) {
                int nl = wn * 64 + nj * 8 + 2 * tp;
                float a0 = acc[mi][nj][h * 2 + 0] - vecs[nl + 0];
                float a1 = acc[mi][nj][h * 2 + 1] - vecs[nl + 1];
                uint32_t vm = max(pkf(a0), pkf(a1));
                vm = max(vm, __shfl_xor_sync(0xFFFFFFFFu, vm, 1));
                vm = max(vm, __shfl_xor_sync(0xFFFFFFFFu, vm, 2));
                if (tp == 0)
                    atomicMax(&g_gmax[(size_t)t * 1024 + ((n0 + wn * 64 + nj * 8) >> 3)], vm);
            }
        }
}

// ===========================================================================
// dist refine: per token, bound-based candidate selection + fp32 rescore.
// ===========================================================================
__global__ __launch_bounds__(256) void dist_refine(const float* __restrict__ cb)
{
    int t = blockIdx.x * 8 + (threadIdx.x >> 5);
    int lane = threadIdx.x & 31;

    float fv[24];
#pragma unroll
    for (int i = 0; i < 24; i++) {
        int k = i * 32 + lane;
        fv[i] = __bfloat162float(g_f3h[(size_t)t * 768 + k])
              + __bfloat162float(g_f3l[(size_t)t * 768 + k]);
    }

    const uint32_t* gm = g_gmax + (size_t)t * 1024;
    uint32_t amax = 0;
    for (int base = 0; base < 1024; base += 32)
        amax = max(amax, gm[base + lane]);
#pragma unroll
    for (int o = 16; o > 0; o >>= 1)
        amax = max(amax, __shfl_xor_sync(0xFFFFFFFFu, amax, o));

    float A = upkf(amax);
    float CL = sqrtf(__uint_as_float(g_clmax2));
    float CT = sqrtf(__uint_as_float(g_ctmax2));
    float M = sqrtf(g_fn2[2 * t]) * CL + sqrtf(g_fn2[2 * t + 1]) * CT;
    float theta = A - 2.f * M - 1.0f;
    uint32_t thp = pkf(theta);

    unsigned long long best = 0ull;
    for (int base = 0; base < 1024; base += 32) {
        uint32_t v = gm[base + lane];
        unsigned msk = __ballot_sync(0xFFFFFFFFu, v >= thp);
        while (msk) {
            int b = __ffs(msk) - 1;
            msk &= msk - 1;
            int g = base + b;
#pragma unroll 1
            for (int cc = 0; cc < 8; cc++) {
                int c = g * 8 + cc;
                const float* crow = cb + (size_t)c * 768;
                float s = 0.f;
#pragma unroll
                for (int i = 0; i < 24; i++)
                    s = fmaf(fv[i], crow[i * 32 + lane], s);
#pragma unroll
                for (int o = 16; o > 0; o >>= 1)
                    s += __shfl_xor_sync(0xFFFFFFFFu, s, o);
                s -= g_c2h[c];
                unsigned long long key = pack_key(s, c);
                best = key > best ? key : best;
            }
        }
    }
    if (lane == 0)
        g_final[t] = 0xFFFFFFFFu - (uint32_t)(best & 0xFFFFFFFFu);
}

// ===========================================================================
// Mega pre-kernel: block-range dispatch. 256 threads.
// ===========================================================================
static constexpr int N_W2 = 384 * 1728;
static constexpr int N_W3 = 768 * 3456;
static constexpr int N_CB = 8192 * 768;
static constexpr int NCVT = N_W2 + N_W3 + N_CB;
static constexpr int NCVB = (NCVT + 255) / 256;
static constexpr int GZ0 = 1024 + NCVB + 256;
static constexpr int MEGA_BLOCKS = GZ0 + 16384;

__global__ __launch_bounds__(256) void mega_pre_kernel(
    const float* __restrict__ image, const float* __restrict__ w1,
    const float* __restrict__ b1, const float* __restrict__ w2,
    const float* __restrict__ w3, const float* __restrict__ cb)
{
    const int blk = blockIdx.x;
    if (blk < 1024) {
        int gt = blk * 256 + threadIdx.x;
        if (gt < 16384) { g_fn2[2 * gt] = 0.f; g_fn2[2 * gt + 1] = 0.f; }
        int v = blk * 8 + (threadIdx.x >> 5);
        int lane = threadIdx.x & 31;
        const float* row = cb + (size_t)v * 768;
        float s2 = 0.f, sl2 = 0.f, st2 = 0.f;
        for (int c = lane; c < 768; c += 32) {
            float x = row[c];
            float hh = __bfloat162float(__float2bfloat16(x));
            float ll = __bfloat162float(__float2bfloat16(x - hh));
            float ct = hh + ll;
            s2 = fmaf(x, x, s2);
            sl2 = fmaf(ll, ll, sl2);
            st2 = fmaf(ct, ct, st2);
        }
#pragma unroll
        for (int o = 16; o > 0; o >>= 1) {
            s2  += __shfl_xor_sync(0xFFFFFFFFu, s2, o);
            sl2 += __shfl_xor_sync(0xFFFFFFFFu, sl2, o);
            st2 += __shfl_xor_sync(0xFFFFFFFFu, st2, o);
        }
        if (lane == 0) {
            g_c2h[v] = 0.5f * s2;
            atomicMax(&g_clmax2, __float_as_uint(sl2));
            atomicMax(&g_ctmax2, __float_as_uint(st2));
        }
        return;
    }
    if (blk < 1024 + NCVB) {
        int i = (blk - 1024) * 256 + threadIdx.x;
        const float* src; __nv_bfloat16 *hi, *lo; int idx;
        if (i < N_W2) { src = w2; hi = g_w2h; lo = g_w2l; idx = i; }
        else if (i < N_W2 + N_W3) { src = w3; hi = g_w3h; lo = g_w3l; idx = i - N_W2; }
        else if (i < NCVT) { src = cb; hi = g_cbh; lo = g_cbl; idx = i - N_W2 - N_W3; }
        else return;
        float v = src[idx];
        __nv_bfloat16 h = __float2bfloat16(v);
        hi[idx] = h;
        lo[idx] = __float2bfloat16(v - __bfloat162float(h));
        return;
    }
    if (blk < GZ0) {
        __shared__ float Ws[192 * 27];
        __shared__ float Bsm[192];
        for (int i = threadIdx.x; i < 192 * 27; i += 256) Ws[i] = w1[i];
        for (int i = threadIdx.x; i < 192; i += 256) Bsm[i] = b1[i];
        __syncthreads();

        int g = (blk - 1024 - NCVB) * 256 + threadIdx.x;
        int x0 = (g & 31) * 4;
        int y = (g >> 5) & 127;
        int b = g >> 12;

        float xv[3][3][9];
        int iy0 = 2 * y - 1;
        int ix0 = 2 * x0 - 1;
#pragma unroll
        for (int ci = 0; ci < 3; ci++)
#pragma unroll
            for (int ky = 0; ky < 3; ky++) {
                int iy = iy0 + ky;
                bool yok = (iy >= 0) && (iy < 256);
                const float* rowp = image + (((size_t)b * 3 + ci) * 256 + iy) * 256;
#pragma unroll
                for (int c = 0; c < 9; c++) {
                    int ix = ix0 + c;
                    xv[ci][ky][c] = (yok && ix >= 0 && ix < 256) ? rowp[ix] : 0.f;
                }
            }

        uint32_t* outp = g_f1i + (size_t)b * 192 * 16384 + y * 128 + x0;
        for (int co = 0; co < 192; co++) {
            float bv = Bsm[co];
            float a0 = bv, a1 = bv, a2 = bv, a3 = bv;
            const float* wp = &Ws[co * 27];
#pragma unroll
            for (int ci = 0; ci < 3; ci++)
#pragma unroll
                for (int ky = 0; ky < 3; ky++)
#pragma unroll
                    for (int kx = 0; kx < 3; kx++) {
                        float wv = wp[ci * 9 + ky * 3 + kx];
                        a0 = fmaf(wv, xv[ci][ky][0 + kx], a0);
                        a1 = fmaf(wv, xv[ci][ky][2 + kx], a1);
                        a2 = fmaf(wv, xv[ci][ky][4 + kx], a2);
                        a3 = fmaf(wv, xv[ci][ky][6 + kx], a3);
                    }
            uint4 r;
            r.x = pack_hl(fmaxf(a0, 0.f));
            r.y = pack_hl(fmaxf(a1, 0.f));
            r.z = pack_hl(fmaxf(a2, 0.f));
            r.w = pack_hl(fmaxf(a3, 0.f));
            *(uint4*)(outp + (size_t)co * 16384) = r;
        }
        return;
    }
    {
        size_t i = (size_t)(blk - GZ0) * 1024 + threadIdx.x * 4;
        *(uint4*)&g_gmax[i] = make_uint4(0, 0, 0, 0);
    }
}

__global__ __launch_bounds__(192) void output_kernel(
    const float* __restrict__ table, float* __restrict__ out)
{
    int p = blockIdx.x;
    unsigned v = g_final[p];
    if (threadIdx.x == 0) out[p] = (float)v;
    float4* dst = (float4*)(out + 16384 + (size_t)p * 768);
    const float4* src = (const float4*)(table + (size_t)v * 768);
    dst[threadIdx.x] = src[threadIdx.x];
}

// ---------------------------------------------------------------------------
extern "C" void kernel_launch(void* const* d_in, const int* in_sizes, int n_in,
                              void* d_out, int out_size)
{
    (void)in_sizes; (void)n_in; (void)out_size;
    const float* image = (const float*)d_in[0];
    const float* w1 = (const float*)d_in[1];
    const float* b1 = (const float*)d_in[2];
    const float* w2 = (const float*)d_in[3];
    const float* b2 = (const float*)d_in[4];
    const float* w3 = (const float*)d_in[5];
    const float* b3 = (const float*)d_in[6];
    const float* cb = (const float*)d_in[7];
    const float* tab = (const float*)d_in[8];
    float* out = (float*)d_out;

    void *pf1, *pf2, *pf3h, *pf3l, *pw2h, *pw2l, *pw3h, *pw3l, *pcbh, *pcbl, *pc2;
    cudaGetSymbolAddress(&pf1, g_f1i);
    cudaGetSymbolAddress(&pf2, g_f2i);
    cudaGetSymbolAddress(&pf3h, g_f3h);
    cudaGetSymbolAddress(&pf3l, g_f3l);
    cudaGetSymbolAddress(&pw2h, g_w2h);
    cudaGetSymbolAddress(&pw2l, g_w2l);
    cudaGetSymbolAddress(&pw3h, g_w3h);
    cudaGetSymbolAddress(&pw3l, g_w3l);
    cudaGetSymbolAddress(&pcbh, g_cbh);
    cudaGetSymbolAddress(&pcbl, g_cbl);
    cudaGetSymbolAddress(&pc2, g_c2h);

    cudaFuncSetAttribute(mma_wide_c2, cudaFuncAttributeMaxDynamicSharedMemorySize, GEMM_SMEM);
    cudaFuncSetAttribute(mma_wide_c3, cudaFuncAttributeMaxDynamicSharedMemorySize, GEMM_SMEM);
    cudaFuncSetAttribute(dist_pass1, cudaFuncAttributeMaxDynamicSharedMemorySize, P1_SMEM);

    // launch 1: prep (c2half/norms + cvt + conv1 + gmax zero)
    mega_pre_kernel<<<MEGA_BLOCKS, 256>>>(image, w1, b1, w2, w3, cb);
    // launch 2: conv2 (WIDE) M=384, N=65536, K=1728
    mma_wide_c2<<<dim3(3, 512), 128, GEMM_SMEM>>>(pw2h, pw2l, pf1, b2, pf2, 1728);
    // launch 3: conv3 (WIDE) M=16384 tokens, N=768, K=3456 (+ norm2 atomics)
    mma_wide_c3<<<dim3(128, 6), 128, GEMM_SMEM>>>(
        pf2, pw3h, pw3l, b3, pf3h, pf3l, 3456);
    // launch 4 (ncu-profiled): dist pass1 (32x64 warps, CTA 64x256), K=768
    dist_pass1<<<dim3(256, 32), 256, P1_SMEM>>>(
        pf3h, pcbh, (const float*)pc2, 768);
    // launch 5: bound-based refine -> g_final
    dist_refine<<<2048, 256>>>(cb);
    // launch 6: decode tokens + gather embeddings
    output_kernel<<<16384, 192>>>(tab, out);
}

// round 15
// speedup vs baseline: 1.1167x; 1.1167x over previous
#include <cuda_runtime.h>
#include <cuda_bf16.h>
#include <cstdint>

// ---------------------------------------------------------------------------
//   mega(1): c2half+cb norms | cvt planes | conv1 | zero gmax/fn2
//   conv2 (WIDE)  -> g_f2i {hi,lo} u32                       [875us]
//   conv3 (WIDE)  -> f3 planes + per-token norm2 atomics     [~780us]
//   dist_pass1 (NARROW 128x128, K-chunk 32, launch#4): 1-term GEMM -> maxima
//   dist_refine: bound-based candidate rescore in fp32 -> g_final
//   R15: pass1 = R11 narrow shape (measured 873us) with K-chunk 16->32:
//        half the syncs/chunk overhead, same cp.async bytes per MMA.
// ---------------------------------------------------------------------------

__device__ uint32_t g_f1i[16u * 192u * 128u * 128u];
__device__ uint32_t g_f2i[16u * 384u * 64u * 64u];
__device__ __nv_bfloat16 g_f3h[16384u * 768u];
__device__ __nv_bfloat16 g_f3l[16384u * 768u];
__device__ __nv_bfloat16 g_w2h[384u * 1728u];
__device__ __nv_bfloat16 g_w2l[384u * 1728u];
__device__ __nv_bfloat16 g_w3h[768u * 3456u];
__device__ __nv_bfloat16 g_w3l[768u * 3456u];
__device__ __nv_bfloat16 g_cbh[8192u * 768u];
__device__ __nv_bfloat16 g_cbl[8192u * 768u];
__device__ float g_c2h[8192];
__device__ float g_fn2[2 * 16384];           // per-token sum fh^2, fl^2
__device__ uint32_t g_clmax2, g_ctmax2;      // max over codes: sum cl^2, sum (ch+cl)^2
__device__ uint32_t g_gmax[16384u * 1024u];  // per (token, 8-code group) packed max
__device__ uint32_t g_final[16384];          // winning code per token

// ------------------------------ helpers -----------------------------------
__device__ __forceinline__ uint32_t smem_u32(const void* p) {
    uint32_t a;
    asm("{ .reg .u64 t; cvta.to.shared.u64 t, %1; cvt.u32.u64 %0, t; }"
        : "=r"(a) : "l"(p));
    return a;
}
__device__ __forceinline__ void ldsm4(uint32_t* r, uint32_t addr) {
    asm volatile("ldmatrix.sync.aligned.m8n8.x4.shared.b16 {%0,%1,%2,%3}, [%4];"
        : "=r"(r[0]), "=r"(r[1]), "=r"(r[2]), "=r"(r[3]) : "r"(addr));
}
__device__ __forceinline__ void mma_bf16(float* c, const uint32_t* a, const uint32_t* b) {
    asm volatile("mma.sync.aligned.m16n8k16.row.col.f32.bf16.bf16.f32 "
        "{%0,%1,%2,%3}, {%4,%5,%6,%7}, {%8,%9}, {%0,%1,%2,%3};"
        : "+f"(c[0]), "+f"(c[1]), "+f"(c[2]), "+f"(c[3])
        : "r"(a[0]), "r"(a[1]), "r"(a[2]), "r"(a[3]), "r"(b[0]), "r"(b[1]));
}
__device__ __forceinline__ uint32_t prmt(uint32_t a, uint32_t b, uint32_t c) {
    uint32_t d;
    asm("prmt.b32 %0, %1, %2, %3;" : "=r"(d) : "r"(a), "r"(b), "r"(c));
    return d;
}
__device__ __forceinline__ void cp16(uint32_t dst, const void* src) {
    asm volatile("cp.async.cg.shared.global [%0], [%1], 16;"
                 :: "r"(dst), "l"(src) : "memory");
}
__device__ __forceinline__ void sts128(uint32_t addr, uint32_t a, uint32_t b,
                                       uint32_t c, uint32_t d) {
    asm volatile("st.shared.v4.b32 [%0], {%1,%2,%3,%4};"
                 :: "r"(addr), "r"(a), "r"(b), "r"(c), "r"(d) : "memory");
}
__device__ __forceinline__ unsigned long long pack_key(float s, int v) {
    unsigned u = __float_as_uint(s);
    u = (u & 0x80000000u) ? ~u : (u | 0x80000000u);
    return ((unsigned long long)u << 32) | (unsigned)(0xFFFFFFFFu - (unsigned)v);
}
__device__ __forceinline__ uint32_t pkf(float s) {      // monotonic float->u32
    uint32_t u = __float_as_uint(s);
    return (u & 0x80000000u) ? ~u : (u | 0x80000000u);
}
__device__ __forceinline__ float upkf(uint32_t u) {
    u = (u & 0x80000000u) ? (u & 0x7FFFFFFFu) : ~u;
    return __uint_as_float(u);
}
__device__ __forceinline__ uint32_t pack_hl(float v) {
    __nv_bfloat16 h = __float2bfloat16(v);
    float hf = __bfloat162float(h);
    __nv_bfloat16 l = __float2bfloat16(v - hf);
    return ((uint32_t)__bfloat16_as_ushort(l) << 16) | __bfloat16_as_ushort(h);
}

static constexpr int TILE = 128 * 48;      // 6144 B (one plane, 128 rows, K16)
static constexpr int STAGE = 4 * TILE;     // Ah,Al,Bh,Bl = 24576 B
static constexpr int NSTAGE = 4;
static constexpr int GEMM_SMEM = NSTAGE * STAGE + 512;

// pass1: K-chunk 32, row stride 80 B (64 data + 16 pad, ldsm conflict-free)
static constexpr int TILE1 = 128 * 80;     // 10240 B per plane (A or B)
static constexpr int STAGE1 = 2 * TILE1;   // 20480 B
static constexpr int NST1 = 4;
static constexpr int P1_SMEM = NST1 * STAGE1 + 1024;   // 82944 B

#define WAITG(n) asm volatile("cp.async.wait_group %0;" :: "n"(n) : "memory")

// ===========================================================================
// WIDE conv2 kernel (measured 875us): 128 threads, 4 warps of 64x64, 2 CTA/SM
// ===========================================================================
__global__ __launch_bounds__(128, 2) void mma_wide_c2(
    const void* __restrict__ pa0, const void* __restrict__ pa1,
    const void* __restrict__ pb0,
    const float* __restrict__ vec, void* __restrict__ o0, int K)
{
    extern __shared__ char sm[];
    const uint32_t sb = smem_u32(sm);
    const int tid = threadIdx.x, wid = tid >> 5, lane = tid & 31;
    const int m0 = blockIdx.x * 128, n0 = blockIdx.y * 128;
    const int NT = K >> 4;

    float* vecs = (float*)(sm + NSTAGE * STAGE);
    vecs[tid] = vec[m0 + tid];

    const char* dirA_h = (const char*)pa0 + (size_t)(m0 + tid) * 1728 * 2;
    const char* dirA_l = (const char*)pa1 + (size_t)(m0 + tid) * 1728 * 2;
    int n = n0 + tid;
    int bb = n >> 12, rem = n & 4095;
    int oy = rem >> 6, ox = rem & 63;
    const uint32_t* gsrc = (const uint32_t*)pb0 + (size_t)bb * (192u * 128u * 128u);
    int giy0 = 2 * oy - 1, gix0 = 2 * ox - 1;

    const uint32_t loff = (uint32_t)tid * 48;
    uint32_t gregs[16];
    uint32_t gst_hi = 0, gst_lo = 0;

    auto issue = [&](int kt, int s) {
        const uint32_t st = sb + (uint32_t)s * STAGE + loff;
        cp16(st,             dirA_h + kt * 32);
        cp16(st + 16,        dirA_h + kt * 32 + 16);
        cp16(st + TILE,      dirA_l + kt * 32);
        cp16(st + TILE + 16, dirA_l + kt * 32 + 16);
        asm volatile("cp.async.commit_group;" ::: "memory");
        const int k0 = kt * 16;
#pragma unroll
        for (int j = 0; j < 16; j++) {
            int k = k0 + j;
            int ci = (k * 7282) >> 16;
            int r = k - ci * 9;
            int ky = (r * 11) >> 5;
            int kx = r - ky * 3;
            int iy = giy0 + ky, ix = gix0 + kx;
            bool ok = (iy >= 0) && (iy < 128) && (ix >= 0) && (ix < 128);
            gregs[j] = ok ? gsrc[(size_t)((ci * 128 + iy) * 128 + ix)] : 0u;
        }
        gst_hi = st + 2 * TILE;
        gst_lo = gst_hi + TILE;
    };
    auto finish = [&]() {
        sts128(gst_hi,      prmt(gregs[0],  gregs[1],  0x5410), prmt(gregs[2],  gregs[3],  0x5410),
                            prmt(gregs[4],  gregs[5],  0x5410), prmt(gregs[6],  gregs[7],  0x5410));
        sts128(gst_hi + 16, prmt(gregs[8],  gregs[9],  0x5410), prmt(gregs[10], gregs[11], 0x5410),
                            prmt(gregs[12], gregs[13], 0x5410), prmt(gregs[14], gregs[15], 0x5410));
        sts128(gst_lo,      prmt(gregs[0],  gregs[1],  0x7632), prmt(gregs[2],  gregs[3],  0x7632),
                            prmt(gregs[4],  gregs[5],  0x7632), prmt(gregs[6],  gregs[7],  0x7632));
        sts128(gst_lo + 16, prmt(gregs[8],  gregs[9],  0x7632), prmt(gregs[10], gregs[11], 0x7632),
                            prmt(gregs[12], gregs[13], 0x7632), prmt(gregs[14], gregs[15], 0x7632));
    };

    const int wm = wid & 1, wn = wid >> 1;
    const int q = lane >> 3, rr = lane & 7;
    const uint32_t a_off = (uint32_t)((wm * 64 + (q & 1) * 8 + rr) * 48 + (q >> 1) * 16);
    const uint32_t b_off = (uint32_t)(((q >> 1) * 8 + rr) * 48 + (q & 1) * 16)
                         + (uint32_t)(wn * 64) * 48;

    float acc[4][8][4];
#pragma unroll
    for (int i = 0; i < 4; i++)
#pragma unroll
        for (int j = 0; j < 8; j++)
#pragma unroll
            for (int e = 0; e < 4; e++) acc[i][j][e] = 0.f;

    issue(0, 0); finish();
    issue(1, 1); finish();
    issue(2, 2); finish();

#pragma unroll 1
    for (int kt = 0; kt < NT; kt++) {
        if (kt + 2 < NT)      WAITG(2);
        else if (kt + 1 < NT) WAITG(1);
        else                  WAITG(0);
        __syncthreads();

        const int s = kt & 3;
        const uint32_t Ah_b = sb + s * STAGE;
        const uint32_t Al_b = Ah_b + TILE;
        const uint32_t Bh_b = Ah_b + 2 * TILE;
        const uint32_t Bl_b = Ah_b + 3 * TILE;

        uint32_t Bh[4][4], Bl[4][4];
#pragma unroll
        for (int ni = 0; ni < 4; ni++) {
            ldsm4(Bh[ni], Bh_b + b_off + ni * 16 * 48);
            ldsm4(Bl[ni], Bl_b + b_off + ni * 16 * 48);
        }
        const bool doNext = (kt + 3 < NT);
        if (doNext) issue(kt + 3, (kt + 3) & 3);

#pragma unroll
        for (int mi = 0; mi < 4; mi++) {
            uint32_t Ah[4], Al[4];
            ldsm4(Ah, Ah_b + a_off + mi * 768);
            ldsm4(Al, Al_b + a_off + mi * 768);
#pragma unroll
            for (int nj = 0; nj < 8; nj++)
                mma_bf16(acc[mi][nj], Ah, &Bh[nj >> 1][(nj & 1) * 2]);
#pragma unroll
            for (int nj = 0; nj < 8; nj++)
                mma_bf16(acc[mi][nj], Ah, &Bl[nj >> 1][(nj & 1) * 2]);
#pragma unroll
            for (int nj = 0; nj < 8; nj++)
                mma_bf16(acc[mi][nj], Al, &Bh[nj >> 1][(nj & 1) * 2]);
        }
        if (doNext) finish();
    }

    const int tg = lane >> 2, tp = lane & 3;
    uint32_t* Ci = (uint32_t*)o0;
    const int obb = n0 >> 12;
    const int sp0 = (n0 & 4095) + wn * 64;
#pragma unroll
    for (int mi = 0; mi < 4; mi++)
#pragma unroll
        for (int h = 0; h < 2; h++) {
            int ml = wm * 64 + mi * 16 + tg + h * 8;
            int m = m0 + ml;
            float bv = vecs[ml];
            uint32_t* rowp = Ci + ((size_t)obb * 384 + m) * 4096;
#pragma unroll
            for (int nj = 0; nj < 8; nj++) {
                float v0 = fmaxf(acc[mi][nj][h * 2 + 0] + bv, 0.f);
                float v1 = fmaxf(acc[mi][nj][h * 2 + 1] + bv, 0.f);
                *(uint2*)(rowp + sp0 + nj * 8 + 2 * tp) =
                    make_uint2(pack_hl(v0), pack_hl(v1));
            }
        }
}

// ===========================================================================
// WIDE conv3 kernel (+ per-token norm2 accumulation in epilogue)
// ===========================================================================
__global__ __launch_bounds__(128, 2) void mma_wide_c3(
    const void* __restrict__ pa0,
    const void* __restrict__ pb0, const void* __restrict__ pb1,
    const float* __restrict__ vec, void* __restrict__ o0,
    void* __restrict__ o1, int K)
{
    extern __shared__ char sm[];
    const uint32_t sb = smem_u32(sm);
    const int tid = threadIdx.x, wid = tid >> 5, lane = tid & 31;
    const int m0 = blockIdx.x * 128, n0 = blockIdx.y * 128;
    const int NT = K >> 4;

    float* vecs = (float*)(sm + NSTAGE * STAGE);
    vecs[tid] = vec[n0 + tid];

    int n = m0 + tid;
    int bb = n >> 10, rem = n & 1023;
    int oy = rem >> 5, ox = rem & 31;
    const uint32_t* gsrc = (const uint32_t*)pa0 + (size_t)bb * (384u * 64u * 64u);
    int giy0 = 2 * oy - 1, gix0 = 2 * ox - 1;
    const char* dirB_h = (const char*)pb0 + (size_t)(n0 + tid) * 3456 * 2;
    const char* dirB_l = (const char*)pb1 + (size_t)(n0 + tid) * 3456 * 2;

    const uint32_t loff = (uint32_t)tid * 48;
    uint32_t gregs[16];
    uint32_t gst_hi = 0, gst_lo = 0;

    auto issue = [&](int kt, int s) {
        const uint32_t st = sb + (uint32_t)s * STAGE + loff;
        cp16(st + 2 * TILE,      dirB_h + kt * 32);
        cp16(st + 2 * TILE + 16, dirB_h + kt * 32 + 16);
        cp16(st + 3 * TILE,      dirB_l + kt * 32);
        cp16(st + 3 * TILE + 16, dirB_l + kt * 32 + 16);
        asm volatile("cp.async.commit_group;" ::: "memory");
        const int k0 = kt * 16;
#pragma unroll
        for (int j = 0; j < 16; j++) {
            int k = k0 + j;
            int ci = (k * 7282) >> 16;
            int r = k - ci * 9;
            int ky = (r * 11) >> 5;
            int kx = r - ky * 3;
            int iy = giy0 + ky, ix = gix0 + kx;
            bool ok = (iy >= 0) && (iy < 64) && (ix >= 0) && (ix < 64);
            gregs[j] = ok ? gsrc[(size_t)((ci * 64 + iy) * 64 + ix)] : 0u;
        }
        gst_hi = st;
        gst_lo = st + TILE;
    };
    auto finish = [&]() {
        sts128(gst_hi,      prmt(gregs[0],  gregs[1],  0x5410), prmt(gregs[2],  gregs[3],  0x5410),
                            prmt(gregs[4],  gregs[5],  0x5410), prmt(gregs[6],  gregs[7],  0x5410));
        sts128(gst_hi + 16, prmt(gregs[8],  gregs[9],  0x5410), prmt(gregs[10], gregs[11], 0x5410),
                            prmt(gregs[12], gregs[13], 0x5410), prmt(gregs[14], gregs[15], 0x5410));
        sts128(gst_lo,      prmt(gregs[0],  gregs[1],  0x7632), prmt(gregs[2],  gregs[3],  0x7632),
                            prmt(gregs[4],  gregs[5],  0x7632), prmt(gregs[6],  gregs[7],  0x7632));
        sts128(gst_lo + 16, prmt(gregs[8],  gregs[9],  0x7632), prmt(gregs[10], gregs[11], 0x7632),
                            prmt(gregs[12], gregs[13], 0x7632), prmt(gregs[14], gregs[15], 0x7632));
    };

    const int wm = wid & 1, wn = wid >> 1;
    const int q = lane >> 3, rr = lane & 7;
    const uint32_t a_off = (uint32_t)((wm * 64 + (q & 1) * 8 + rr) * 48 + (q >> 1) * 16);
    const uint32_t b_off = (uint32_t)(((q >> 1) * 8 + rr) * 48 + (q & 1) * 16)
                         + (uint32_t)(wn * 64) * 48;

    float acc[4][8][4];
#pragma unroll
    for (int i = 0; i < 4; i++)
#pragma unroll
        for (int j = 0; j < 8; j++)
#pragma unroll
            for (int e = 0; e < 4; e++) acc[i][j][e] = 0.f;

    issue(0, 0); finish();
    issue(1, 1); finish();
    issue(2, 2); finish();

#pragma unroll 1
    for (int kt = 0; kt < NT; kt++) {
        if (kt + 2 < NT)      WAITG(2);
        else if (kt + 1 < NT) WAITG(1);
        else                  WAITG(0);
        __syncthreads();

        const int s = kt & 3;
        const uint32_t Ah_b = sb + s * STAGE;
        const uint32_t Al_b = Ah_b + TILE;
        const uint32_t Bh_b = Ah_b + 2 * TILE;
        const uint32_t Bl_b = Ah_b + 3 * TILE;

        uint32_t Bh[4][4], Bl[4][4];
#pragma unroll
        for (int ni = 0; ni < 4; ni++) {
            ldsm4(Bh[ni], Bh_b + b_off + ni * 16 * 48);
            ldsm4(Bl[ni], Bl_b + b_off + ni * 16 * 48);
        }
        const bool doNext = (kt + 3 < NT);
        if (doNext) issue(kt + 3, (kt + 3) & 3);

#pragma unroll
        for (int mi = 0; mi < 4; mi++) {
            uint32_t Ah[4], Al[4];
            ldsm4(Ah, Ah_b + a_off + mi * 768);
            ldsm4(Al, Al_b + a_off + mi * 768);
#pragma unroll
            for (int nj = 0; nj < 8; nj++)
                mma_bf16(acc[mi][nj], Ah, &Bh[nj >> 1][(nj & 1) * 2]);
#pragma unroll
            for (int nj = 0; nj < 8; nj++)
                mma_bf16(acc[mi][nj], Ah, &Bl[nj >> 1][(nj & 1) * 2]);
#pragma unroll
            for (int nj = 0; nj < 8; nj++)
                mma_bf16(acc[mi][nj], Al, &Bh[nj >> 1][(nj & 1) * 2]);
        }
        if (doNext) finish();
    }

    const int tg = lane >> 2, tp = lane & 3;
    __nv_bfloat16* fh = (__nv_bfloat16*)o0;
    __nv_bfloat16* fl = (__nv_bfloat16*)o1;
#pragma unroll
    for (int mi = 0; mi < 4; mi++)
#pragma unroll
        for (int h = 0; h < 2; h++) {
            int m = m0 + wm * 64 + mi * 16 + tg + h * 8;   // token
            __nv_bfloat16* rowh = fh + (size_t)m * 768 + n0;
            __nv_bfloat16* rowl = fl + (size_t)m * 768 + n0;
            float sh2 = 0.f, sl2 = 0.f;
#pragma unroll
            for (int nj = 0; nj < 8; nj++) {
                int nl = wn * 64 + nj * 8 + 2 * tp;
                float v0 = acc[mi][nj][h * 2 + 0] + vecs[nl + 0];
                float v1 = acc[mi][nj][h * 2 + 1] + vecs[nl + 1];
                __nv_bfloat16 h0 = __float2bfloat16(v0);
                __nv_bfloat16 h1 = __float2bfloat16(v1);
                float h0f = __bfloat162float(h0), h1f = __bfloat162float(h1);
                __nv_bfloat16 l0 = __float2bfloat16(v0 - h0f);
                __nv_bfloat16 l1 = __float2bfloat16(v1 - h1f);
                float l0f = __bfloat162float(l0), l1f = __bfloat162float(l1);
                sh2 += h0f * h0f + h1f * h1f;
                sl2 += l0f * l0f + l1f * l1f;
                *(__nv_bfloat162*)(rowh + nl) = __nv_bfloat162(h0, h1);
                *(__nv_bfloat162*)(rowl + nl) = __nv_bfloat162(l0, l1);
            }
            sh2 += __shfl_xor_sync(0xFFFFFFFFu, sh2, 1);
            sh2 += __shfl_xor_sync(0xFFFFFFFFu, sh2, 2);
            sl2 += __shfl_xor_sync(0xFFFFFFFFu, sl2, 1);
            sl2 += __shfl_xor_sync(0xFFFFFFFFu, sl2, 2);
            if (tp == 0) {
                atomicAdd(&g_fn2[2 * m],     sh2);
                atomicAdd(&g_fn2[2 * m + 1], sl2);
            }
        }
}

// ===========================================================================
// dist pass1 (R15): NARROW 128x128 CTA, 8 warps of 64x32, 2 CTA/SM,
// K-chunk 32 (row stride 80B). 1-term GEMM fh*ch -> per-group atomicMax.
// ===========================================================================
__global__ __launch_bounds__(256, 2) void dist_pass1(
    const void* __restrict__ pa0, const void* __restrict__ pb0,
    const float* __restrict__ vec, int K)
{
    extern __shared__ char sm[];
    const uint32_t sb = smem_u32(sm);
    const int tid = threadIdx.x, wid = tid >> 5, lane = tid & 31;
    const int m0 = blockIdx.x * 128, n0 = blockIdx.y * 128;
    const int NT = K >> 5;                 // 24 chunks of K=32

    float* vecs = (float*)(sm + NST1 * STAGE1);
    if (tid < 128) vecs[tid] = vec[n0 + tid];

    // loaders: row = tid>>1 (128 rows), half = tid&1 (32B each)
    const int lrow = tid >> 1, lhalf = tid & 1;
    const char* dirA_h = (const char*)pa0 + ((size_t)(m0 + lrow) * 768 + lhalf * 16) * 2;
    const char* dirB_h = (const char*)pb0 + ((size_t)(n0 + lrow) * 768 + lhalf * 16) * 2;
    const uint32_t loff = (uint32_t)(lrow * 80 + lhalf * 32);

    auto load_chunk = [&](int kt, int s) {
        const uint32_t st = sb + (uint32_t)s * STAGE1 + loff;
        cp16(st,              dirA_h + kt * 64);
        cp16(st + 16,         dirA_h + kt * 64 + 16);
        cp16(st + TILE1,      dirB_h + kt * 64);
        cp16(st + TILE1 + 16, dirB_h + kt * 64 + 16);
        asm volatile("cp.async.commit_group;" ::: "memory");
    };

    // warp tiling: 2 (m, 64 rows) x 4 (n, 32 cols)
    const int wm = wid & 1, wn = wid >> 1;
    const int q = lane >> 3, rr = lane & 7;
    const uint32_t a_off = (uint32_t)((wm * 64 + (q & 1) * 8 + rr) * 80 + (q >> 1) * 16);
    const uint32_t b_off = (uint32_t)(((q >> 1) * 8 + rr) * 80 + (q & 1) * 16)
                         + (uint32_t)(wn * 32) * 80;

    float acc[4][4][4];
#pragma unroll
    for (int i = 0; i < 4; i++)
#pragma unroll
        for (int j = 0; j < 4; j++)
#pragma unroll
            for (int e = 0; e < 4; e++) acc[i][j][e] = 0.f;

    load_chunk(0, 0);
    load_chunk(1, 1);
    load_chunk(2, 2);

#pragma unroll 1
    for (int kt = 0; kt < NT; kt++) {
        if (kt + 2 < NT)      WAITG(2);
        else if (kt + 1 < NT) WAITG(1);
        else                  WAITG(0);
        __syncthreads();

        const int s = kt & 3;
        const uint32_t Ab = sb + (uint32_t)s * STAGE1;
        const uint32_t Bb = Ab + TILE1;

        if (kt + 3 < NT) load_chunk(kt + 3, (kt + 3) & 3);

#pragma unroll
        for (int kk = 0; kk < 2; kk++) {       // two K16 steps per chunk
            uint32_t Bh[2][4];
            ldsm4(Bh[0], Bb + b_off + kk * 32);
            ldsm4(Bh[1], Bb + b_off + kk * 32 + 16 * 80);
#pragma unroll
            for (int mi = 0; mi < 4; mi++) {
                uint32_t Ah[4];
                ldsm4(Ah, Ab + a_off + kk * 32 + mi * 16 * 80);
#pragma unroll
                for (int nj = 0; nj < 4; nj++)
                    mma_bf16(acc[mi][nj], Ah, &Bh[nj >> 1][(nj & 1) * 2]);
            }
        }
    }

    const int tg = lane >> 2, tp = lane & 3;
#pragma unroll
    for (int mi = 0; mi < 4; mi++)
#pragma unroll
        for (int h = 0; h < 2; h++) {
            int t = m0 + wm * 64 + mi * 16 + tg + h * 8;   // token
#pragma unroll
            for (int nj = 0; nj < 4; nj++) {
                int nl = wn * 32 + nj * 8 + 2 * tp;
                float a0 = acc[mi][nj][h * 2 + 0] - vecs[nl + 0];
                float a1 = acc[mi][nj][h * 2 + 1] - vecs[nl + 1];
                uint32_t vm = max(pkf(a0), pkf(a1));
                vm = max(vm, __shfl_xor_sync(0xFFFFFFFFu, vm, 1));
                vm = max(vm, __shfl_xor_sync(0xFFFFFFFFu, vm, 2));
                if (tp == 0)
                    atomicMax(&g_gmax[(size_t)t * 1024 + ((n0 + wn * 32 + nj * 8) >> 3)], vm);
            }
        }
}

// ===========================================================================
// dist refine: per token, bound-based candidate selection + fp32 rescore.
// ===========================================================================
__global__ __launch_bounds__(256) void dist_refine(const float* __restrict__ cb)
{
    int t = blockIdx.x * 8 + (threadIdx.x >> 5);
    int lane = threadIdx.x & 31;

    float fv[24];
#pragma unroll
    for (int i = 0; i < 24; i++) {
        int k = i * 32 + lane;
        fv[i] = __bfloat162float(g_f3h[(size_t)t * 768 + k])
              + __bfloat162float(g_f3l[(size_t)t * 768 + k]);
    }

    const uint32_t* gm = g_gmax + (size_t)t * 1024;
    uint32_t amax = 0;
    for (int base = 0; base < 1024; base += 32)
        amax = max(amax, gm[base + lane]);
#pragma unroll
    for (int o = 16; o > 0; o >>= 1)
        amax = max(amax, __shfl_xor_sync(0xFFFFFFFFu, amax, o));

    float A = upkf(amax);
    float CL = sqrtf(__uint_as_float(g_clmax2));
    float CT = sqrtf(__uint_as_float(g_ctmax2));
    float M = sqrtf(g_fn2[2 * t]) * CL + sqrtf(g_fn2[2 * t + 1]) * CT;
    float theta = A - 2.f * M - 1.0f;
    uint32_t thp = pkf(theta);

    unsigned long long best = 0ull;
    for (int base = 0; base < 1024; base += 32) {
        uint32_t v = gm[base + lane];
        unsigned msk = __ballot_sync(0xFFFFFFFFu, v >= thp);
        while (msk) {
            int b = __ffs(msk) - 1;
            msk &= msk - 1;
            int g = base + b;
#pragma unroll 1
            for (int cc = 0; cc < 8; cc++) {
                int c = g * 8 + cc;
                const float* crow = cb + (size_t)c * 768;
                float s = 0.f;
#pragma unroll
                for (int i = 0; i < 24; i++)
                    s = fmaf(fv[i], crow[i * 32 + lane], s);
#pragma unroll
                for (int o = 16; o > 0; o >>= 1)
                    s += __shfl_xor_sync(0xFFFFFFFFu, s, o);
                s -= g_c2h[c];
                unsigned long long key = pack_key(s, c);
                best = key > best ? key : best;
            }
        }
    }
    if (lane == 0)
        g_final[t] = 0xFFFFFFFFu - (uint32_t)(best & 0xFFFFFFFFu);
}

// ===========================================================================
// Mega pre-kernel: block-range dispatch. 256 threads.
// ===========================================================================
static constexpr int N_W2 = 384 * 1728;
static constexpr int N_W3 = 768 * 3456;
static constexpr int N_CB = 8192 * 768;
static constexpr int NCVT = N_W2 + N_W3 + N_CB;
static constexpr int NCVB = (NCVT + 255) / 256;
static constexpr int GZ0 = 1024 + NCVB + 256;
static constexpr int MEGA_BLOCKS = GZ0 + 16384;

__global__ __launch_bounds__(256) void mega_pre_kernel(
    const float* __restrict__ image, const float* __restrict__ w1,
    const float* __restrict__ b1, const float* __restrict__ w2,
    const float* __restrict__ w3, const float* __restrict__ cb)
{
    const int blk = blockIdx.x;
    if (blk < 1024) {
        int gt = blk * 256 + threadIdx.x;
        if (gt < 16384) { g_fn2[2 * gt] = 0.f; g_fn2[2 * gt + 1] = 0.f; }
        int v = blk * 8 + (threadIdx.x >> 5);
        int lane = threadIdx.x & 31;
        const float* row = cb + (size_t)v * 768;
        float s2 = 0.f, sl2 = 0.f, st2 = 0.f;
        for (int c = lane; c < 768; c += 32) {
            float x = row[c];
            float hh = __bfloat162float(__float2bfloat16(x));
            float ll = __bfloat162float(__float2bfloat16(x - hh));
            float ct = hh + ll;
            s2 = fmaf(x, x, s2);
            sl2 = fmaf(ll, ll, sl2);
            st2 = fmaf(ct, ct, st2);
        }
#pragma unroll
        for (int o = 16; o > 0; o >>= 1) {
            s2  += __shfl_xor_sync(0xFFFFFFFFu, s2, o);
            sl2 += __shfl_xor_sync(0xFFFFFFFFu, sl2, o);
            st2 += __shfl_xor_sync(0xFFFFFFFFu, st2, o);
        }
        if (lane == 0) {
            g_c2h[v] = 0.5f * s2;
            atomicMax(&g_clmax2, __float_as_uint(sl2));
            atomicMax(&g_ctmax2, __float_as_uint(st2));
        }
        return;
    }
    if (blk < 1024 + NCVB) {
        int i = (blk - 1024) * 256 + threadIdx.x;
        const float* src; __nv_bfloat16 *hi, *lo; int idx;
        if (i < N_W2) { src = w2; hi = g_w2h; lo = g_w2l; idx = i; }
        else if (i < N_W2 + N_W3) { src = w3; hi = g_w3h; lo = g_w3l; idx = i - N_W2; }
        else if (i < NCVT) { src = cb; hi = g_cbh; lo = g_cbl; idx = i - N_W2 - N_W3; }
        else return;
        float v = src[idx];
        __nv_bfloat16 h = __float2bfloat16(v);
        hi[idx] = h;
        lo[idx] = __float2bfloat16(v - __bfloat162float(h));
        return;
    }
    if (blk < GZ0) {
        __shared__ float Ws[192 * 27];
        __shared__ float Bsm[192];
        for (int i = threadIdx.x; i < 192 * 27; i += 256) Ws[i] = w1[i];
        for (int i = threadIdx.x; i < 192; i += 256) Bsm[i] = b1[i];
        __syncthreads();

        int g = (blk - 1024 - NCVB) * 256 + threadIdx.x;
        int x0 = (g & 31) * 4;
        int y = (g >> 5) & 127;
        int b = g >> 12;

        float xv[3][3][9];
        int iy0 = 2 * y - 1;
        int ix0 = 2 * x0 - 1;
#pragma unroll
        for (int ci = 0; ci < 3; ci++)
#pragma unroll
            for (int ky = 0; ky < 3; ky++) {
                int iy = iy0 + ky;
                bool yok = (iy >= 0) && (iy < 256);
                const float* rowp = image + (((size_t)b * 3 + ci) * 256 + iy) * 256;
#pragma unroll
                for (int c = 0; c < 9; c++) {
                    int ix = ix0 + c;
                    xv[ci][ky][c] = (yok && ix >= 0 && ix < 256) ? rowp[ix] : 0.f;
                }
            }

        uint32_t* outp = g_f1i + (size_t)b * 192 * 16384 + y * 128 + x0;
        for (int co = 0; co < 192; co++) {
            float bv = Bsm[co];
            float a0 = bv, a1 = bv, a2 = bv, a3 = bv;
            const float* wp = &Ws[co * 27];
#pragma unroll
            for (int ci = 0; ci < 3; ci++)
#pragma unroll
                for (int ky = 0; ky < 3; ky++)
#pragma unroll
                    for (int kx = 0; kx < 3; kx++) {
                        float wv = wp[ci * 9 + ky * 3 + kx];
                        a0 = fmaf(wv, xv[ci][ky][0 + kx], a0);
                        a1 = fmaf(wv, xv[ci][ky][2 + kx], a1);
                        a2 = fmaf(wv, xv[ci][ky][4 + kx], a2);
                        a3 = fmaf(wv, xv[ci][ky][6 + kx], a3);
                    }
            uint4 r;
            r.x = pack_hl(fmaxf(a0, 0.f));
            r.y = pack_hl(fmaxf(a1, 0.f));
            r.z = pack_hl(fmaxf(a2, 0.f));
            r.w = pack_hl(fmaxf(a3, 0.f));
            *(uint4*)(outp + (size_t)co * 16384) = r;
        }
        return;
    }
    {
        size_t i = (size_t)(blk - GZ0) * 1024 + threadIdx.x * 4;
        *(uint4*)&g_gmax[i] = make_uint4(0, 0, 0, 0);
    }
}

__global__ __launch_bounds__(192) void output_kernel(
    const float* __restrict__ table, float* __restrict__ out)
{
    int p = blockIdx.x;
    unsigned v = g_final[p];
    if (threadIdx.x == 0) out[p] = (float)v;
    float4* dst = (float4*)(out + 16384 + (size_t)p * 768);
    const float4* src = (const float4*)(table + (size_t)v * 768);
    dst[threadIdx.x] = src[threadIdx.x];
}

// ---------------------------------------------------------------------------
extern "C" void kernel_launch(void* const* d_in, const int* in_sizes, int n_in,
                              void* d_out, int out_size)
{
    (void)in_sizes; (void)n_in; (void)out_size;
    const float* image = (const float*)d_in[0];
    const float* w1 = (const float*)d_in[1];
    const float* b1 = (const float*)d_in[2];
    const float* w2 = (const float*)d_in[3];
    const float* b2 = (const float*)d_in[4];
    const float* w3 = (const float*)d_in[5];
    const float* b3 = (const float*)d_in[6];
    const float* cb = (const float*)d_in[7];
    const float* tab = (const float*)d_in[8];
    float* out = (float*)d_out;

    void *pf1, *pf2, *pf3h, *pf3l, *pw2h, *pw2l, *pw3h, *pw3l, *pcbh, *pcbl, *pc2;
    cudaGetSymbolAddress(&pf1, g_f1i);
    cudaGetSymbolAddress(&pf2, g_f2i);
    cudaGetSymbolAddress(&pf3h, g_f3h);
    cudaGetSymbolAddress(&pf3l, g_f3l);
    cudaGetSymbolAddress(&pw2h, g_w2h);
    cudaGetSymbolAddress(&pw2l, g_w2l);
    cudaGetSymbolAddress(&pw3h, g_w3h);
    cudaGetSymbolAddress(&pw3l, g_w3l);
    cudaGetSymbolAddress(&pcbh, g_cbh);
    cudaGetSymbolAddress(&pcbl, g_cbl);
    cudaGetSymbolAddress(&pc2, g_c2h);

    cudaFuncSetAttribute(mma_wide_c2, cudaFuncAttributeMaxDynamicSharedMemorySize, GEMM_SMEM);
    cudaFuncSetAttribute(mma_wide_c3, cudaFuncAttributeMaxDynamicSharedMemorySize, GEMM_SMEM);
    cudaFuncSetAttribute(dist_pass1, cudaFuncAttributeMaxDynamicSharedMemorySize, P1_SMEM);

    // launch 1: prep (c2half/norms + cvt + conv1 + gmax zero)
    mega_pre_kernel<<<MEGA_BLOCKS, 256>>>(image, w1, b1, w2, w3, cb);
    // launch 2: conv2 (WIDE) M=384, N=65536, K=1728
    mma_wide_c2<<<dim3(3, 512), 128, GEMM_SMEM>>>(pw2h, pw2l, pf1, b2, pf2, 1728);
    // launch 3: conv3 (WIDE) M=16384 tokens, N=768, K=3456 (+ norm2 atomics)
    mma_wide_c3<<<dim3(128, 6), 128, GEMM_SMEM>>>(
        pf2, pw3h, pw3l, b3, pf3h, pf3l, 3456);
    // launch 4 (ncu-profiled): dist pass1 (NARROW, K-chunk 32), M=16384, N=8192
    dist_pass1<<<dim3(128, 64), 256, P1_SMEM>>>(
        pf3h, pcbh, (const float*)pc2, 768);
    // launch 5: bound-based refine -> g_final
    dist_refine<<<2048, 256>>>(cb);
    // launch 6: decode tokens + gather embeddings
    output_kernel<<<16384, 192>>>(tab, out);
}

// round 16
// speedup vs baseline: 1.1372x; 1.0184x over previous
#include <cuda_runtime.h>
#include <cuda_bf16.h>
#include <cstdint>

// ---------------------------------------------------------------------------
//   mega(1): c2half+cb norms | cvt planes | conv1 | zero gmax/fn2
//   conv2 (WIDE)  -> g_f2i {hi,lo} u32                       [875us]
//   conv3 (WIDE)  -> f3 planes + per-token norm2 atomics     [~780us]
//   dist_pass1 (NARROW, R11 exact, launch#4): 1-term GEMM -> 16-code group maxima
//   dist_refine: bound-based candidate rescore in fp32 -> g_final
//   R16: R11 config re-banked + gmax groups 8->16 (32MB table: half the
//        zeroing, half the pass1 atomics, half the refine scan).
// ---------------------------------------------------------------------------

__device__ uint32_t g_f1i[16u * 192u * 128u * 128u];
__device__ uint32_t g_f2i[16u * 384u * 64u * 64u];
__device__ __nv_bfloat16 g_f3h[16384u * 768u];
__device__ __nv_bfloat16 g_f3l[16384u * 768u];
__device__ __nv_bfloat16 g_w2h[384u * 1728u];
__device__ __nv_bfloat16 g_w2l[384u * 1728u];
__device__ __nv_bfloat16 g_w3h[768u * 3456u];
__device__ __nv_bfloat16 g_w3l[768u * 3456u];
__device__ __nv_bfloat16 g_cbh[8192u * 768u];
__device__ __nv_bfloat16 g_cbl[8192u * 768u];
__device__ float g_c2h[8192];
__device__ float g_fn2[2 * 16384];           // per-token sum fh^2, fl^2
__device__ uint32_t g_clmax2, g_ctmax2;      // max over codes: sum cl^2, sum (ch+cl)^2
__device__ uint32_t g_gmax[16384u * 512u];   // per (token, 16-code group) packed max
__device__ uint32_t g_final[16384];          // winning code per token

// ------------------------------ helpers -----------------------------------
__device__ __forceinline__ uint32_t smem_u32(const void* p) {
    uint32_t a;
    asm("{ .reg .u64 t; cvta.to.shared.u64 t, %1; cvt.u32.u64 %0, t; }"
        : "=r"(a) : "l"(p));
    return a;
}
__device__ __forceinline__ void ldsm4(uint32_t* r, uint32_t addr) {
    asm volatile("ldmatrix.sync.aligned.m8n8.x4.shared.b16 {%0,%1,%2,%3}, [%4];"
        : "=r"(r[0]), "=r"(r[1]), "=r"(r[2]), "=r"(r[3]) : "r"(addr));
}
__device__ __forceinline__ void mma_bf16(float* c, const uint32_t* a, const uint32_t* b) {
    asm volatile("mma.sync.aligned.m16n8k16.row.col.f32.bf16.bf16.f32 "
        "{%0,%1,%2,%3}, {%4,%5,%6,%7}, {%8,%9}, {%0,%1,%2,%3};"
        : "+f"(c[0]), "+f"(c[1]), "+f"(c[2]), "+f"(c[3])
        : "r"(a[0]), "r"(a[1]), "r"(a[2]), "r"(a[3]), "r"(b[0]), "r"(b[1]));
}
__device__ __forceinline__ uint32_t prmt(uint32_t a, uint32_t b, uint32_t c) {
    uint32_t d;
    asm("prmt.b32 %0, %1, %2, %3;" : "=r"(d) : "r"(a), "r"(b), "r"(c));
    return d;
}
__device__ __forceinline__ void cp16(uint32_t dst, const void* src) {
    asm volatile("cp.async.cg.shared.global [%0], [%1], 16;"
                 :: "r"(dst), "l"(src) : "memory");
}
__device__ __forceinline__ void sts128(uint32_t addr, uint32_t a, uint32_t b,
                                       uint32_t c, uint32_t d) {
    asm volatile("st.shared.v4.b32 [%0], {%1,%2,%3,%4};"
                 :: "r"(addr), "r"(a), "r"(b), "r"(c), "r"(d) : "memory");
}
__device__ __forceinline__ unsigned long long pack_key(float s, int v) {
    unsigned u = __float_as_uint(s);
    u = (u & 0x80000000u) ? ~u : (u | 0x80000000u);
    return ((unsigned long long)u << 32) | (unsigned)(0xFFFFFFFFu - (unsigned)v);
}
__device__ __forceinline__ uint32_t pkf(float s) {      // monotonic float->u32
    uint32_t u = __float_as_uint(s);
    return (u & 0x80000000u) ? ~u : (u | 0x80000000u);
}
__device__ __forceinline__ float upkf(uint32_t u) {
    u = (u & 0x80000000u) ? (u & 0x7FFFFFFFu) : ~u;
    return __uint_as_float(u);
}
__device__ __forceinline__ uint32_t pack_hl(float v) {
    __nv_bfloat16 h = __float2bfloat16(v);
    float hf = __bfloat162float(h);
    __nv_bfloat16 l = __float2bfloat16(v - hf);
    return ((uint32_t)__bfloat16_as_ushort(l) << 16) | __bfloat16_as_ushort(h);
}

static constexpr int TILE = 128 * 48;      // 6144 B (one plane, 128 rows, K16)
static constexpr int STAGE = 4 * TILE;     // Ah,Al,Bh,Bl = 24576 B
static constexpr int NSTAGE = 4;
static constexpr int GEMM_SMEM = NSTAGE * STAGE + 512;

static constexpr int STAGE1 = 2 * TILE;    // pass1: Ah,Bh only
static constexpr int P1_SMEM = 4 * STAGE1 + 512;

#define WAITG(n) asm volatile("cp.async.wait_group %0;" :: "n"(n) : "memory")

// ===========================================================================
// WIDE conv2 kernel (measured 875us): 128 threads, 4 warps of 64x64, 2 CTA/SM
// ===========================================================================
__global__ __launch_bounds__(128, 2) void mma_wide_c2(
    const void* __restrict__ pa0, const void* __restrict__ pa1,
    const void* __restrict__ pb0,
    const float* __restrict__ vec, void* __restrict__ o0, int K)
{
    extern __shared__ char sm[];
    const uint32_t sb = smem_u32(sm);
    const int tid = threadIdx.x, wid = tid >> 5, lane = tid & 31;
    const int m0 = blockIdx.x * 128, n0 = blockIdx.y * 128;
    const int NT = K >> 4;

    float* vecs = (float*)(sm + NSTAGE * STAGE);
    vecs[tid] = vec[m0 + tid];

    const char* dirA_h = (const char*)pa0 + (size_t)(m0 + tid) * 1728 * 2;
    const char* dirA_l = (const char*)pa1 + (size_t)(m0 + tid) * 1728 * 2;
    int n = n0 + tid;
    int bb = n >> 12, rem = n & 4095;
    int oy = rem >> 6, ox = rem & 63;
    const uint32_t* gsrc = (const uint32_t*)pb0 + (size_t)bb * (192u * 128u * 128u);
    int giy0 = 2 * oy - 1, gix0 = 2 * ox - 1;

    const uint32_t loff = (uint32_t)tid * 48;
    uint32_t gregs[16];
    uint32_t gst_hi = 0, gst_lo = 0;

    auto issue = [&](int kt, int s) {
        const uint32_t st = sb + (uint32_t)s * STAGE + loff;
        cp16(st,             dirA_h + kt * 32);
        cp16(st + 16,        dirA_h + kt * 32 + 16);
        cp16(st + TILE,      dirA_l + kt * 32);
        cp16(st + TILE + 16, dirA_l + kt * 32 + 16);
        asm volatile("cp.async.commit_group;" ::: "memory");
        const int k0 = kt * 16;
#pragma unroll
        for (int j = 0; j < 16; j++) {
            int k = k0 + j;
            int ci = (k * 7282) >> 16;
            int r = k - ci * 9;
            int ky = (r * 11) >> 5;
            int kx = r - ky * 3;
            int iy = giy0 + ky, ix = gix0 + kx;
            bool ok = (iy >= 0) && (iy < 128) && (ix >= 0) && (ix < 128);
            gregs[j] = ok ? gsrc[(size_t)((ci * 128 + iy) * 128 + ix)] : 0u;
        }
        gst_hi = st + 2 * TILE;
        gst_lo = gst_hi + TILE;
    };
    auto finish = [&]() {
        sts128(gst_hi,      prmt(gregs[0],  gregs[1],  0x5410), prmt(gregs[2],  gregs[3],  0x5410),
                            prmt(gregs[4],  gregs[5],  0x5410), prmt(gregs[6],  gregs[7],  0x5410));
        sts128(gst_hi + 16, prmt(gregs[8],  gregs[9],  0x5410), prmt(gregs[10], gregs[11], 0x5410),
                            prmt(gregs[12], gregs[13], 0x5410), prmt(gregs[14], gregs[15], 0x5410));
        sts128(gst_lo,      prmt(gregs[0],  gregs[1],  0x7632), prmt(gregs[2],  gregs[3],  0x7632),
                            prmt(gregs[4],  gregs[5],  0x7632), prmt(gregs[6],  gregs[7],  0x7632));
        sts128(gst_lo + 16, prmt(gregs[8],  gregs[9],  0x7632), prmt(gregs[10], gregs[11], 0x7632),
                            prmt(gregs[12], gregs[13], 0x7632), prmt(gregs[14], gregs[15], 0x7632));
    };

    const int wm = wid & 1, wn = wid >> 1;
    const int q = lane >> 3, rr = lane & 7;
    const uint32_t a_off = (uint32_t)((wm * 64 + (q & 1) * 8 + rr) * 48 + (q >> 1) * 16);
    const uint32_t b_off = (uint32_t)(((q >> 1) * 8 + rr) * 48 + (q & 1) * 16)
                         + (uint32_t)(wn * 64) * 48;

    float acc[4][8][4];
#pragma unroll
    for (int i = 0; i < 4; i++)
#pragma unroll
        for (int j = 0; j < 8; j++)
#pragma unroll
            for (int e = 0; e < 4; e++) acc[i][j][e] = 0.f;

    issue(0, 0); finish();
    issue(1, 1); finish();
    issue(2, 2); finish();

#pragma unroll 1
    for (int kt = 0; kt < NT; kt++) {
        if (kt + 2 < NT)      WAITG(2);
        else if (kt + 1 < NT) WAITG(1);
        else                  WAITG(0);
        __syncthreads();

        const int s = kt & 3;
        const uint32_t Ah_b = sb + s * STAGE;
        const uint32_t Al_b = Ah_b + TILE;
        const uint32_t Bh_b = Ah_b + 2 * TILE;
        const uint32_t Bl_b = Ah_b + 3 * TILE;

        uint32_t Bh[4][4], Bl[4][4];
#pragma unroll
        for (int ni = 0; ni < 4; ni++) {
            ldsm4(Bh[ni], Bh_b + b_off + ni * 16 * 48);
            ldsm4(Bl[ni], Bl_b + b_off + ni * 16 * 48);
        }
        const bool doNext = (kt + 3 < NT);
        if (doNext) issue(kt + 3, (kt + 3) & 3);

#pragma unroll
        for (int mi = 0; mi < 4; mi++) {
            uint32_t Ah[4], Al[4];
            ldsm4(Ah, Ah_b + a_off + mi * 768);
            ldsm4(Al, Al_b + a_off + mi * 768);
#pragma unroll
            for (int nj = 0; nj < 8; nj++)
                mma_bf16(acc[mi][nj], Ah, &Bh[nj >> 1][(nj & 1) * 2]);
#pragma unroll
            for (int nj = 0; nj < 8; nj++)
                mma_bf16(acc[mi][nj], Ah, &Bl[nj >> 1][(nj & 1) * 2]);
#pragma unroll
            for (int nj = 0; nj < 8; nj++)
                mma_bf16(acc[mi][nj], Al, &Bh[nj >> 1][(nj & 1) * 2]);
        }
        if (doNext) finish();
    }

    const int tg = lane >> 2, tp = lane & 3;
    uint32_t* Ci = (uint32_t*)o0;
    const int obb = n0 >> 12;
    const int sp0 = (n0 & 4095) + wn * 64;
#pragma unroll
    for (int mi = 0; mi < 4; mi++)
#pragma unroll
        for (int h = 0; h < 2; h++) {
            int ml = wm * 64 + mi * 16 + tg + h * 8;
            int m = m0 + ml;
            float bv = vecs[ml];
            uint32_t* rowp = Ci + ((size_t)obb * 384 + m) * 4096;
#pragma unroll
            for (int nj = 0; nj < 8; nj++) {
                float v0 = fmaxf(acc[mi][nj][h * 2 + 0] + bv, 0.f);
                float v1 = fmaxf(acc[mi][nj][h * 2 + 1] + bv, 0.f);
                *(uint2*)(rowp + sp0 + nj * 8 + 2 * tp) =
                    make_uint2(pack_hl(v0), pack_hl(v1));
            }
        }
}

// ===========================================================================
// WIDE conv3 kernel (+ per-token norm2 accumulation in epilogue)
// ===========================================================================
__global__ __launch_bounds__(128, 2) void mma_wide_c3(
    const void* __restrict__ pa0,
    const void* __restrict__ pb0, const void* __restrict__ pb1,
    const float* __restrict__ vec, void* __restrict__ o0,
    void* __restrict__ o1, int K)
{
    extern __shared__ char sm[];
    const uint32_t sb = smem_u32(sm);
    const int tid = threadIdx.x, wid = tid >> 5, lane = tid & 31;
    const int m0 = blockIdx.x * 128, n0 = blockIdx.y * 128;
    const int NT = K >> 4;

    float* vecs = (float*)(sm + NSTAGE * STAGE);
    vecs[tid] = vec[n0 + tid];

    int n = m0 + tid;
    int bb = n >> 10, rem = n & 1023;
    int oy = rem >> 5, ox = rem & 31;
    const uint32_t* gsrc = (const uint32_t*)pa0 + (size_t)bb * (384u * 64u * 64u);
    int giy0 = 2 * oy - 1, gix0 = 2 * ox - 1;
    const char* dirB_h = (const char*)pb0 + (size_t)(n0 + tid) * 3456 * 2;
    const char* dirB_l = (const char*)pb1 + (size_t)(n0 + tid) * 3456 * 2;

    const uint32_t loff = (uint32_t)tid * 48;
    uint32_t gregs[16];
    uint32_t gst_hi = 0, gst_lo = 0;

    auto issue = [&](int kt, int s) {
        const uint32_t st = sb + (uint32_t)s * STAGE + loff;
        cp16(st + 2 * TILE,      dirB_h + kt * 32);
        cp16(st + 2 * TILE + 16, dirB_h + kt * 32 + 16);
        cp16(st + 3 * TILE,      dirB_l + kt * 32);
        cp16(st + 3 * TILE + 16, dirB_l + kt * 32 + 16);
        asm volatile("cp.async.commit_group;" ::: "memory");
        const int k0 = kt * 16;
#pragma unroll
        for (int j = 0; j < 16; j++) {
            int k = k0 + j;
            int ci = (k * 7282) >> 16;
            int r = k - ci * 9;
            int ky = (r * 11) >> 5;
            int kx = r - ky * 3;
            int iy = giy0 + ky, ix = gix0 + kx;
            bool ok = (iy >= 0) && (iy < 64) && (ix >= 0) && (ix < 64);
            gregs[j] = ok ? gsrc[(size_t)((ci * 64 + iy) * 64 + ix)] : 0u;
        }
        gst_hi = st;
        gst_lo = st + TILE;
    };
    auto finish = [&]() {
        sts128(gst_hi,      prmt(gregs[0],  gregs[1],  0x5410), prmt(gregs[2],  gregs[3],  0x5410),
                            prmt(gregs[4],  gregs[5],  0x5410), prmt(gregs[6],  gregs[7],  0x5410));
        sts128(gst_hi + 16, prmt(gregs[8],  gregs[9],  0x5410), prmt(gregs[10], gregs[11], 0x5410),
                            prmt(gregs[12], gregs[13], 0x5410), prmt(gregs[14], gregs[15], 0x5410));
        sts128(gst_lo,      prmt(gregs[0],  gregs[1],  0x7632), prmt(gregs[2],  gregs[3],  0x7632),
                            prmt(gregs[4],  gregs[5],  0x7632), prmt(gregs[6],  gregs[7],  0x7632));
        sts128(gst_lo + 16, prmt(gregs[8],  gregs[9],  0x7632), prmt(gregs[10], gregs[11], 0x7632),
                            prmt(gregs[12], gregs[13], 0x7632), prmt(gregs[14], gregs[15], 0x7632));
    };

    const int wm = wid & 1, wn = wid >> 1;
    const int q = lane >> 3, rr = lane & 7;
    const uint32_t a_off = (uint32_t)((wm * 64 + (q & 1) * 8 + rr) * 48 + (q >> 1) * 16);
    const uint32_t b_off = (uint32_t)(((q >> 1) * 8 + rr) * 48 + (q & 1) * 16)
                         + (uint32_t)(wn * 64) * 48;

    float acc[4][8][4];
#pragma unroll
    for (int i = 0; i < 4; i++)
#pragma unroll
        for (int j = 0; j < 8; j++)
#pragma unroll
            for (int e = 0; e < 4; e++) acc[i][j][e] = 0.f;

    issue(0, 0); finish();
    issue(1, 1); finish();
    issue(2, 2); finish();

#pragma unroll 1
    for (int kt = 0; kt < NT; kt++) {
        if (kt + 2 < NT)      WAITG(2);
        else if (kt + 1 < NT) WAITG(1);
        else                  WAITG(0);
        __syncthreads();

        const int s = kt & 3;
        const uint32_t Ah_b = sb + s * STAGE;
        const uint32_t Al_b = Ah_b + TILE;
        const uint32_t Bh_b = Ah_b + 2 * TILE;
        const uint32_t Bl_b = Ah_b + 3 * TILE;

        uint32_t Bh[4][4], Bl[4][4];
#pragma unroll
        for (int ni = 0; ni < 4; ni++) {
            ldsm4(Bh[ni], Bh_b + b_off + ni * 16 * 48);
            ldsm4(Bl[ni], Bl_b + b_off + ni * 16 * 48);
        }
        const bool doNext = (kt + 3 < NT);
        if (doNext) issue(kt + 3, (kt + 3) & 3);

#pragma unroll
        for (int mi = 0; mi < 4; mi++) {
            uint32_t Ah[4], Al[4];
            ldsm4(Ah, Ah_b + a_off + mi * 768);
            ldsm4(Al, Al_b + a_off + mi * 768);
#pragma unroll
            for (int nj = 0; nj < 8; nj++)
                mma_bf16(acc[mi][nj], Ah, &Bh[nj >> 1][(nj & 1) * 2]);
#pragma unroll
            for (int nj = 0; nj < 8; nj++)
                mma_bf16(acc[mi][nj], Ah, &Bl[nj >> 1][(nj & 1) * 2]);
#pragma unroll
            for (int nj = 0; nj < 8; nj++)
                mma_bf16(acc[mi][nj], Al, &Bh[nj >> 1][(nj & 1) * 2]);
        }
        if (doNext) finish();
    }

    const int tg = lane >> 2, tp = lane & 3;
    __nv_bfloat16* fh = (__nv_bfloat16*)o0;
    __nv_bfloat16* fl = (__nv_bfloat16*)o1;
#pragma unroll
    for (int mi = 0; mi < 4; mi++)
#pragma unroll
        for (int h = 0; h < 2; h++) {
            int m = m0 + wm * 64 + mi * 16 + tg + h * 8;   // token
            __nv_bfloat16* rowh = fh + (size_t)m * 768 + n0;
            __nv_bfloat16* rowl = fl + (size_t)m * 768 + n0;
            float sh2 = 0.f, sl2 = 0.f;
#pragma unroll
            for (int nj = 0; nj < 8; nj++) {
                int nl = wn * 64 + nj * 8 + 2 * tp;
                float v0 = acc[mi][nj][h * 2 + 0] + vecs[nl + 0];
                float v1 = acc[mi][nj][h * 2 + 1] + vecs[nl + 1];
                __nv_bfloat16 h0 = __float2bfloat16(v0);
                __nv_bfloat16 h1 = __float2bfloat16(v1);
                float h0f = __bfloat162float(h0), h1f = __bfloat162float(h1);
                __nv_bfloat16 l0 = __float2bfloat16(v0 - h0f);
                __nv_bfloat16 l1 = __float2bfloat16(v1 - h1f);
                float l0f = __bfloat162float(l0), l1f = __bfloat162float(l1);
                sh2 += h0f * h0f + h1f * h1f;
                sl2 += l0f * l0f + l1f * l1f;
                *(__nv_bfloat162*)(rowh + nl) = __nv_bfloat162(h0, h1);
                *(__nv_bfloat162*)(rowl + nl) = __nv_bfloat162(l0, l1);
            }
            sh2 += __shfl_xor_sync(0xFFFFFFFFu, sh2, 1);
            sh2 += __shfl_xor_sync(0xFFFFFFFFu, sh2, 2);
            sl2 += __shfl_xor_sync(0xFFFFFFFFu, sl2, 1);
            sl2 += __shfl_xor_sync(0xFFFFFFFFu, sl2, 2);
            if (tp == 0) {
                atomicAdd(&g_fn2[2 * m],     sh2);
                atomicAdd(&g_fn2[2 * m + 1], sl2);
            }
        }
}

// ===========================================================================
// dist pass1 (NARROW, R11 exact): 256 threads, 8 warps of 64x32, 2 CTA/SM.
// 1-term GEMM fh*ch. Epilogue: per-(token, 16-code group) atomicMax.
// ===========================================================================
__global__ __launch_bounds__(256, 2) void dist_pass1(
    const void* __restrict__ pa0, const void* __restrict__ pb0,
    const float* __restrict__ vec, int K)
{
    extern __shared__ char sm[];
    const uint32_t sb = smem_u32(sm);
    const int tid = threadIdx.x, wid = tid >> 5, lane = tid & 31;
    const int m0 = blockIdx.x * 128, n0 = blockIdx.y * 128;
    const int NT = K >> 4;

    float* vecs = (float*)(sm + 4 * STAGE1);
    if (tid < 128) vecs[tid] = vec[n0 + tid];

    const int lrow = tid >> 1, lhalf = tid & 1;
    const char* dirA_h = (const char*)pa0 + ((size_t)(m0 + lrow) * 768 + lhalf * 8) * 2;
    const char* dirB_h = (const char*)pb0 + ((size_t)(n0 + lrow) * 768 + lhalf * 8) * 2;
    const uint32_t loff = (uint32_t)(lrow * 48 + lhalf * 16);

    auto load_chunk = [&](int kt, int s) {
        const uint32_t st = sb + s * STAGE1 + loff;
        cp16(st,         dirA_h + kt * 32);
        cp16(st + TILE,  dirB_h + kt * 32);
        asm volatile("cp.async.commit_group;" ::: "memory");
    };

    const int wm = wid & 1, wn = wid >> 1;
    const int q = lane >> 3, rr = lane & 7;
    const uint32_t a_off = (uint32_t)((wm * 64 + (q & 1) * 8 + rr) * 48 + (q >> 1) * 16);
    const uint32_t b_off = (uint32_t)(((q >> 1) * 8 + rr) * 48 + (q & 1) * 16)
                         + (uint32_t)(wn * 32) * 48;

    float acc[4][4][4];
#pragma unroll
    for (int i = 0; i < 4; i++)
#pragma unroll
        for (int j = 0; j < 4; j++)
#pragma unroll
            for (int e = 0; e < 4; e++) acc[i][j][e] = 0.f;

    load_chunk(0, 0);
    load_chunk(1, 1);
    load_chunk(2, 2);

#pragma unroll 1
    for (int kt = 0; kt < NT; kt++) {
        if (kt + 2 < NT)      WAITG(2);
        else if (kt + 1 < NT) WAITG(1);
        else                  WAITG(0);
        __syncthreads();

        const int s = kt & 3;
        const uint32_t Ah_b = sb + s * STAGE1;
        const uint32_t Bh_b = Ah_b + TILE;

        uint32_t Bh[2][4];
        ldsm4(Bh[0], Bh_b + b_off);
        ldsm4(Bh[1], Bh_b + b_off + 16 * 48);
#pragma unroll
        for (int mi = 0; mi < 4; mi++) {
            uint32_t Ah[4];
            ldsm4(Ah, Ah_b + a_off + mi * 768);
#pragma unroll
            for (int nj = 0; nj < 4; nj++)
                mma_bf16(acc[mi][nj], Ah, &Bh[nj >> 1][(nj & 1) * 2]);
        }
        if (kt + 3 < NT) load_chunk(kt + 3, (kt + 3) & 3);
    }

    const int tg = lane >> 2, tp = lane & 3;
#pragma unroll
    for (int mi = 0; mi < 4; mi++)
#pragma unroll
        for (int h = 0; h < 2; h++) {
            int t = m0 + wm * 64 + mi * 16 + tg + h * 8;   // token
#pragma unroll
            for (int nj2 = 0; nj2 < 2; nj2++) {            // 16-code group
                uint32_t vm = 0;
#pragma unroll
                for (int e = 0; e < 2; e++) {
                    int nj = nj2 * 2 + e;
                    int nl = wn * 32 + nj * 8 + 2 * tp;
                    vm = max(vm, max(pkf(acc[mi][nj][h * 2 + 0] - vecs[nl + 0]),
                                     pkf(acc[mi][nj][h * 2 + 1] - vecs[nl + 1])));
                }
                vm = max(vm, __shfl_xor_sync(0xFFFFFFFFu, vm, 1));
                vm = max(vm, __shfl_xor_sync(0xFFFFFFFFu, vm, 2));
                if (tp == 0)
                    atomicMax(&g_gmax[(size_t)t * 512 + ((n0 + wn * 32 + nj2 * 16) >> 4)], vm);
            }
        }
}

// ===========================================================================
// dist refine: per token, bound-based candidate selection + fp32 rescore.
// ===========================================================================
__global__ __launch_bounds__(256) void dist_refine(const float* __restrict__ cb)
{
    int t = blockIdx.x * 8 + (threadIdx.x >> 5);
    int lane = threadIdx.x & 31;

    float fv[24];
#pragma unroll
    for (int i = 0; i < 24; i++) {
        int k = i * 32 + lane;
        fv[i] = __bfloat162float(g_f3h[(size_t)t * 768 + k])
              + __bfloat162float(g_f3l[(size_t)t * 768 + k]);
    }

    const uint32_t* gm = g_gmax + (size_t)t * 512;
    uint32_t amax = 0;
    for (int base = 0; base < 512; base += 32)
        amax = max(amax, gm[base + lane]);
#pragma unroll
    for (int o = 16; o > 0; o >>= 1)
        amax = max(amax, __shfl_xor_sync(0xFFFFFFFFu, amax, o));

    float A = upkf(amax);
    float CL = sqrtf(__uint_as_float(g_clmax2));
    float CT = sqrtf(__uint_as_float(g_ctmax2));
    float M = sqrtf(g_fn2[2 * t]) * CL + sqrtf(g_fn2[2 * t + 1]) * CT;
    float theta = A - 2.f * M - 1.0f;
    uint32_t thp = pkf(theta);

    unsigned long long best = 0ull;
    for (int base = 0; base < 512; base += 32) {
        uint32_t v = gm[base + lane];
        unsigned msk = __ballot_sync(0xFFFFFFFFu, v >= thp);
        while (msk) {
            int b = __ffs(msk) - 1;
            msk &= msk - 1;
            int g = base + b;
#pragma unroll 1
            for (int cc = 0; cc < 16; cc++) {
                int c = g * 16 + cc;
                const float* crow = cb + (size_t)c * 768;
                float s = 0.f;
#pragma unroll
                for (int i = 0; i < 24; i++)
                    s = fmaf(fv[i], crow[i * 32 + lane], s);
#pragma unroll
                for (int o = 16; o > 0; o >>= 1)
                    s += __shfl_xor_sync(0xFFFFFFFFu, s, o);
                s -= g_c2h[c];
                unsigned long long key = pack_key(s, c);
                best = key > best ? key : best;
            }
        }
    }
    if (lane == 0)
        g_final[t] = 0xFFFFFFFFu - (uint32_t)(best & 0xFFFFFFFFu);
}

// ===========================================================================
// Mega pre-kernel: block-range dispatch. 256 threads.
// ===========================================================================
static constexpr int N_W2 = 384 * 1728;
static constexpr int N_W3 = 768 * 3456;
static constexpr int N_CB = 8192 * 768;
static constexpr int NCVT = N_W2 + N_W3 + N_CB;
static constexpr int NCVB = (NCVT + 255) / 256;
static constexpr int GZ0 = 1024 + NCVB + 256;
static constexpr int MEGA_BLOCKS = GZ0 + 16384;   // gmax zero: 16384 blocks x 512 u32

__global__ __launch_bounds__(256) void mega_pre_kernel(
    const float* __restrict__ image, const float* __restrict__ w1,
    const float* __restrict__ b1, const float* __restrict__ w2,
    const float* __restrict__ w3, const float* __restrict__ cb)
{
    const int blk = blockIdx.x;
    if (blk < 1024) {
        int gt = blk * 256 + threadIdx.x;
        if (gt < 16384) { g_fn2[2 * gt] = 0.f; g_fn2[2 * gt + 1] = 0.f; }
        int v = blk * 8 + (threadIdx.x >> 5);
        int lane = threadIdx.x & 31;
        const float* row = cb + (size_t)v * 768;
        float s2 = 0.f, sl2 = 0.f, st2 = 0.f;
        for (int c = lane; c < 768; c += 32) {
            float x = row[c];
            float hh = __bfloat162float(__float2bfloat16(x));
            float ll = __bfloat162float(__float2bfloat16(x - hh));
            float ct = hh + ll;
            s2 = fmaf(x, x, s2);
            sl2 = fmaf(ll, ll, sl2);
            st2 = fmaf(ct, ct, st2);
        }
#pragma unroll
        for (int o = 16; o > 0; o >>= 1) {
            s2  += __shfl_xor_sync(0xFFFFFFFFu, s2, o);
            sl2 += __shfl_xor_sync(0xFFFFFFFFu, sl2, o);
            st2 += __shfl_xor_sync(0xFFFFFFFFu, st2, o);
        }
        if (lane == 0) {
            g_c2h[v] = 0.5f * s2;
            atomicMax(&g_clmax2, __float_as_uint(sl2));
            atomicMax(&g_ctmax2, __float_as_uint(st2));
        }
        return;
    }
    if (blk < 1024 + NCVB) {
        int i = (blk - 1024) * 256 + threadIdx.x;
        const float* src; __nv_bfloat16 *hi, *lo; int idx;
        if (i < N_W2) { src = w2; hi = g_w2h; lo = g_w2l; idx = i; }
        else if (i < N_W2 + N_W3) { src = w3; hi = g_w3h; lo = g_w3l; idx = i - N_W2; }
        else if (i < NCVT) { src = cb; hi = g_cbh; lo = g_cbl; idx = i - N_W2 - N_W3; }
        else return;
        float v = src[idx];
        __nv_bfloat16 h = __float2bfloat16(v);
        hi[idx] = h;
        lo[idx] = __float2bfloat16(v - __bfloat162float(h));
        return;
    }
    if (blk < GZ0) {
        __shared__ float Ws[192 * 27];
        __shared__ float Bsm[192];
        for (int i = threadIdx.x; i < 192 * 27; i += 256) Ws[i] = w1[i];
        for (int i = threadIdx.x; i < 192; i += 256) Bsm[i] = b1[i];
        __syncthreads();

        int g = (blk - 1024 - NCVB) * 256 + threadIdx.x;
        int x0 = (g & 31) * 4;
        int y = (g >> 5) & 127;
        int b = g >> 12;

        float xv[3][3][9];
        int iy0 = 2 * y - 1;
        int ix0 = 2 * x0 - 1;
#pragma unroll
        for (int ci = 0; ci < 3; ci++)
#pragma unroll
            for (int ky = 0; ky < 3; ky++) {
                int iy = iy0 + ky;
                bool yok = (iy >= 0) && (iy < 256);
                const float* rowp = image + (((size_t)b * 3 + ci) * 256 + iy) * 256;
#pragma unroll
                for (int c = 0; c < 9; c++) {
                    int ix = ix0 + c;
                    xv[ci][ky][c] = (yok && ix >= 0 && ix < 256) ? rowp[ix] : 0.f;
                }
            }

        uint32_t* outp = g_f1i + (size_t)b * 192 * 16384 + y * 128 + x0;
        for (int co = 0; co < 192; co++) {
            float bv = Bsm[co];
            float a0 = bv, a1 = bv, a2 = bv, a3 = bv;
            const float* wp = &Ws[co * 27];
#pragma unroll
            for (int ci = 0; ci < 3; ci++)
#pragma unroll
                for (int ky = 0; ky < 3; ky++)
#pragma unroll
                    for (int kx = 0; kx < 3; kx++) {
                        float wv = wp[ci * 9 + ky * 3 + kx];
                        a0 = fmaf(wv, xv[ci][ky][0 + kx], a0);
                        a1 = fmaf(wv, xv[ci][ky][2 + kx], a1);
                        a2 = fmaf(wv, xv[ci][ky][4 + kx], a2);
                        a3 = fmaf(wv, xv[ci][ky][6 + kx], a3);
                    }
            uint4 r;
            r.x = pack_hl(fmaxf(a0, 0.f));
            r.y = pack_hl(fmaxf(a1, 0.f));
            r.z = pack_hl(fmaxf(a2, 0.f));
            r.w = pack_hl(fmaxf(a3, 0.f));
            *(uint4*)(outp + (size_t)co * 16384) = r;
        }
        return;
    }
    {
        // zero g_gmax: 16384 blocks x 512 u32; 128 threads x uint4
        if (threadIdx.x < 128) {
            size_t i = (size_t)(blk - GZ0) * 512 + threadIdx.x * 4;
            *(uint4*)&g_gmax[i] = make_uint4(0, 0, 0, 0);
        }
    }
}

__global__ __launch_bounds__(192) void output_kernel(
    const float* __restrict__ table, float* __restrict__ out)
{
    int p = blockIdx.x;
    unsigned v = g_final[p];
    if (threadIdx.x == 0) out[p] = (float)v;
    float4* dst = (float4*)(out + 16384 + (size_t)p * 768);
    const float4* src = (const float4*)(table + (size_t)v * 768);
    dst[threadIdx.x] = src[threadIdx.x];
}

// ---------------------------------------------------------------------------
extern "C" void kernel_launch(void* const* d_in, const int* in_sizes, int n_in,
                              void* d_out, int out_size)
{
    (void)in_sizes; (void)n_in; (void)out_size;
    const float* image = (const float*)d_in[0];
    const float* w1 = (const float*)d_in[1];
    const float* b1 = (const float*)d_in[2];
    const float* w2 = (const float*)d_in[3];
    const float* b2 = (const float*)d_in[4];
    const float* w3 = (const float*)d_in[5];
    const float* b3 = (const float*)d_in[6];
    const float* cb = (const float*)d_in[7];
    const float* tab = (const float*)d_in[8];
    float* out = (float*)d_out;

    void *pf1, *pf2, *pf3h, *pf3l, *pw2h, *pw2l, *pw3h, *pw3l, *pcbh, *pcbl, *pc2;
    cudaGetSymbolAddress(&pf1, g_f1i);
    cudaGetSymbolAddress(&pf2, g_f2i);
    cudaGetSymbolAddress(&pf3h, g_f3h);
    cudaGetSymbolAddress(&pf3l, g_f3l);
    cudaGetSymbolAddress(&pw2h, g_w2h);
    cudaGetSymbolAddress(&pw2l, g_w2l);
    cudaGetSymbolAddress(&pw3h, g_w3h);
    cudaGetSymbolAddress(&pw3l, g_w3l);
    cudaGetSymbolAddress(&pcbh, g_cbh);
    cudaGetSymbolAddress(&pcbl, g_cbl);
    cudaGetSymbolAddress(&pc2, g_c2h);

    cudaFuncSetAttribute(mma_wide_c2, cudaFuncAttributeMaxDynamicSharedMemorySize, GEMM_SMEM);
    cudaFuncSetAttribute(mma_wide_c3, cudaFuncAttributeMaxDynamicSharedMemorySize, GEMM_SMEM);
    cudaFuncSetAttribute(dist_pass1, cudaFuncAttributeMaxDynamicSharedMemorySize, P1_SMEM);

    // launch 1: prep (c2half/norms + cvt + conv1 + gmax zero)
    mega_pre_kernel<<<MEGA_BLOCKS, 256>>>(image, w1, b1, w2, w3, cb);
    // launch 2: conv2 (WIDE) M=384, N=65536, K=1728
    mma_wide_c2<<<dim3(3, 512), 128, GEMM_SMEM>>>(pw2h, pw2l, pf1, b2, pf2, 1728);
    // launch 3: conv3 (WIDE) M=16384 tokens, N=768, K=3456 (+ norm2 atomics)
    mma_wide_c3<<<dim3(128, 6), 128, GEMM_SMEM>>>(
        pf2, pw3h, pw3l, b3, pf3h, pf3l, 3456);
    // launch 4 (ncu-profiled): dist pass1 (NARROW, R11), M=16384, N=8192, K=768
    dist_pass1<<<dim3(128, 64), 256, P1_SMEM>>>(
        pf3h, pcbh, (const float*)pc2, 768);
    // launch 5: bound-based refine -> g_final
    dist_refine<<<2048, 256>>>(cb);
    // launch 6: decode tokens + gather embeddings
    output_kernel<<<16384, 192>>>(tab, out);
}